// round 12
// baseline (speedup 1.0000x reference)
#include <cuda_runtime.h>
#include <cuda_bf16.h>
#include <cuda_fp16.h>
#include <math.h>

// ---------------- problem constants ----------------
#define HH 8
#define DD 16
#define FF 128
#define F3 384
#define NLAYER 2
#define NTYPE 3
#define NREL 4
#define NTOT 80000
#define KRTOT 120000
#define ETOT 600000
#define KSTR 32                        // packed k-chunk stride (elems), XOR-swizzled
#define PLANE (128 * KSTR)             // 4096 elems = 8KB
#define GEMM_SMEM (2 * 4 * PLANE * 2)  // 64KB -> 2 CTAs/SM

// folded qkv weights: [L][T][5 segs][128 n][128 k]
#define W2SEG 16384
#define W2PER (5 * W2SEG)
#define W2TOT (NLAYER * NTYPE * W2PER)          // 491520
#define OUTW_ELEMS (NLAYER * NTYPE * FF * FF)   //  98304
#define WALL (W2TOT + OUTW_ELEMS)

// block-mapping constants
#define MT0 391
#define MT1 157
#define MT2 79
#define QKV_B0 (5 * MT0)
#define QKV_B1 MT1
#define QKV_BLOCKS (QKV_B0 + QKV_B1 + 5 * MT2)   // 2507
#define OUT_BLOCKS (MT0 + MT1 + MT2)             // 627

// ---------------- device scratch ----------------
__device__ __align__(16) float g_x0[NTOT * FF];
__device__ __align__(16) float g_x1[NTOT * FF];
__device__ __align__(16) float g_q[NTOT * FF];
__device__ __align__(16) __half g_krh[KRTOT * FF];
__device__ __align__(16) __half g_vrh[KRTOT * FF];
__device__ __align__(16) __nv_bfloat16 g_ah[NTOT * FF];
__device__ __align__(16) __nv_bfloat16 g_al[NTOT * FF];
__device__ __align__(16) __nv_bfloat16 g_wh[WALL];
__device__ __align__(16) __nv_bfloat16 g_wl[WALL];
__device__ float g_b2[NLAYER * NTYPE * 5 * FF];
__device__ int g_deg[NTOT];
__device__ int g_off[NTOT + 1];
__device__ int g_cursor[NTOT];
__device__ int g_csr[ETOT];      // (r << 20) | (kroff + src)

__device__ __forceinline__ float gelu_f(float x) {
    return 0.5f * x * (1.f + erff(x * 0.70710678118654752440f));
}

// swizzled element offset of 16B chunk j (0..3) of row r (0..127)
__device__ __forceinline__ int swoff(int r, int j) {
    return (r << 5) + ((j ^ (r & 3) ^ ((r >> 2) & 1)) << 3);
}

// ---------------- setup kernels ----------------

__global__ void copyin_split_kernel(const float* __restrict__ xg,
                                    const float* __restrict__ xd,
                                    const float* __restrict__ xr) {
    int tid = blockIdx.x * blockDim.x + threadIdx.x;
    if (tid < NTOT) g_deg[tid] = 0;           // fused CSR-degree reset
    long i8 = (long)tid * 8;
    if (i8 >= (long)NTOT * FF) return;
    const long n1 = 50000L * FF, n2 = 70000L * FF;
    const float* src;
    long off;
    if (i8 < n1)      { src = xg; off = i8; }
    else if (i8 < n2) { src = xd; off = i8 - n1; }
    else              { src = xr; off = i8 - n2; }
    float v[8];
    *(float4*)&v[0] = *(const float4*)&src[off];
    *(float4*)&v[4] = *(const float4*)&src[off + 4];
    *(float4*)&g_x0[i8]     = *(const float4*)&v[0];
    *(float4*)&g_x0[i8 + 4] = *(const float4*)&v[4];
    __nv_bfloat16 h[8], l[8];
#pragma unroll
    for (int j = 0; j < 8; j++) {
        h[j] = __float2bfloat16_rn(v[j]);
        l[j] = __float2bfloat16_rn(v[j] - __bfloat162float(h[j]));
    }
    *(uint4*)&g_ah[i8] = *(const uint4*)&h[0];
    *(uint4*)&g_al[i8] = *(const uint4*)&l[0];
}

__global__ void fold_kernel(const float* __restrict__ Wkqv,
                            const float* __restrict__ Ak,
                            const float* __restrict__ Av) {
    int idx = blockIdx.x * blockDim.x + threadIdx.x;
    if (idx >= W2TOT) return;
    int k = idx & 127;
    int n = (idx >> 7) & 127;
    int sl = idx >> 14;
    int seg = sl % 5, lt = sl / 5;
    int l = lt / NTYPE, t = lt % NTYPE;
    const float* W = Wkqv + (long)lt * FF * F3;
    float val = 0.f;
    if (seg == 0) {
        val = W[(long)k * F3 + FF + n];
    } else if (t != 1) {
        int r = (t == 0 ? 0 : 2) + ((seg == 2 || seg == 4) ? 1 : 0);
        int h = n >> 4, e = n & 15;
        const float* A = ((seg <= 2) ? Ak : Av) +
                         ((long)(l * NREL + r) * HH + h) * DD * DD;
        int colbase = (seg <= 2 ? 0 : 2 * FF) + h * DD;
#pragma unroll
        for (int d = 0; d < DD; d++)
            val += W[(long)k * F3 + colbase + d] * A[d * DD + e];
    }
    __nv_bfloat16 hi = __float2bfloat16_rn(val);
    g_wh[idx] = hi;
    g_wl[idx] = __float2bfloat16_rn(val - __bfloat162float(hi));
}

__global__ void foldb_kernel(const float* __restrict__ bkqv,
                             const float* __restrict__ Ak,
                             const float* __restrict__ Av) {
    int idx = blockIdx.x * blockDim.x + threadIdx.x;
    if (idx >= NLAYER * NTYPE * 5 * FF) return;
    int n = idx & 127;
    int sl = idx >> 7;
    int seg = sl % 5, lt = sl / 5;
    int l = lt / NTYPE, t = lt % NTYPE;
    const float* b = bkqv + (long)lt * F3;
    float val = 0.f;
    if (seg == 0) {
        val = b[FF + n];
    } else if (t != 1) {
        int r = (t == 0 ? 0 : 2) + ((seg == 2 || seg == 4) ? 1 : 0);
        int h = n >> 4, e = n & 15;
        const float* A = ((seg <= 2) ? Ak : Av) +
                         ((long)(l * NREL + r) * HH + h) * DD * DD;
        int colbase = (seg <= 2 ? 0 : 2 * FF) + h * DD;
#pragma unroll
        for (int d = 0; d < DD; d++)
            val += b[colbase + d] * A[d * DD + e];
    }
    g_b2[idx] = val;
}

__global__ void splitw_kernel(const float* __restrict__ Wout) {
    int idx = blockIdx.x * blockDim.x + threadIdx.x;
    if (idx >= OUTW_ELEMS) return;
    int lt = idx / (FF * FF);
    int rem = idx - lt * (FF * FF);
    int n = rem / FF, k = rem % FF;
    float val = Wout[(long)lt * FF * FF + (long)k * FF + n];
    __nv_bfloat16 hi = __float2bfloat16_rn(val);
    g_wh[W2TOT + idx] = hi;
    g_wl[W2TOT + idx] = __float2bfloat16_rn(val - __bfloat162float(hi));
}

// ---------------- CSR build ----------------

__device__ __forceinline__ void edge_decode(int e, const int* e0, const int* e1,
                                            const int* e2, const int* e3,
                                            int& r, int& off, const int*& ep,
                                            int& E, int& dt_off, int& kroff) {
    if (e < 300000)      { r = 0; off = e;          ep = e0; E = 300000; dt_off = 0;     kroff = 0; }
    else if (e < 450000) { r = 1; off = e - 300000; ep = e1; E = 150000; dt_off = 50000; kroff = 50000; }
    else if (e < 550000) { r = 2; off = e - 450000; ep = e2; E = 100000; dt_off = 0;     kroff = 100000; }
    else                 { r = 3; off = e - 550000; ep = e3; E = 50000;  dt_off = 50000; kroff = 110000; }
}

__global__ void hist_all_kernel(const int* __restrict__ e0, const int* __restrict__ e1,
                                const int* __restrict__ e2, const int* __restrict__ e3) {
    int e = blockIdx.x * blockDim.x + threadIdx.x;
    if (e >= ETOT) return;
    int r, off, E, dt_off, kroff;
    const int* ep;
    edge_decode(e, e0, e1, e2, e3, r, off, ep, E, dt_off, kroff);
    atomicAdd(&g_deg[dt_off + ep[E + off]], 1);
}

__global__ void scan_kernel() {
    __shared__ int s[1024];
    int t = threadIdx.x;
    const int CHUNK = 79;
    int base = t * CHUNK;
    int sum = 0;
    for (int i = 0; i < CHUNK; i++) {
        int idx = base + i;
        if (idx < NTOT) sum += g_deg[idx];
    }
    s[t] = sum;
    __syncthreads();
    for (int d = 1; d < 1024; d <<= 1) {
        int v = (t >= d) ? s[t - d] : 0;
        __syncthreads();
        s[t] += v;
        __syncthreads();
    }
    int run = (t == 0) ? 0 : s[t - 1];
    for (int i = 0; i < CHUNK; i++) {
        int idx = base + i;
        if (idx < NTOT) {
            g_off[idx] = run;
            g_cursor[idx] = run;
            run += g_deg[idx];
        }
    }
    if (t == 0) g_off[NTOT] = ETOT;
}

__global__ void scatter_all_kernel(const int* __restrict__ e0, const int* __restrict__ e1,
                                   const int* __restrict__ e2, const int* __restrict__ e3) {
    int e = blockIdx.x * blockDim.x + threadIdx.x;
    if (e >= ETOT) return;
    int r, off, E, dt_off, kroff;
    const int* ep;
    edge_decode(e, e0, e1, e2, e3, r, off, ep, E, dt_off, kroff);
    int pos = atomicAdd(&g_cursor[dt_off + ep[E + off]], 1);
    g_csr[pos] = (r << 20) | (kroff + ep[off]);
}

// ---------------- tensor-core GEMM core ----------------
#define LDSM4(r, addr) \
    asm volatile("ldmatrix.sync.aligned.m8n8.x4.shared.b16 {%0,%1,%2,%3}, [%4];" \
        : "=r"((r)[0]), "=r"((r)[1]), "=r"((r)[2]), "=r"((r)[3]) : "r"(addr))

#define MMA16816(c, a0, a1, a2, a3, b0, b1) \
    asm volatile("mma.sync.aligned.m16n8k16.row.col.f32.bf16.bf16.f32 " \
        "{%0,%1,%2,%3}, {%4,%5,%6,%7}, {%8,%9}, {%0,%1,%2,%3};" \
        : "+f"((c)[0]), "+f"((c)[1]), "+f"((c)[2]), "+f"((c)[3]) \
        : "r"(a0), "r"(a1), "r"(a2), "r"(a3), "r"(b0), "r"(b1))

__device__ __forceinline__ void cp16(__nv_bfloat16* dst, const __nv_bfloat16* src,
                                     int srcsize) {
    unsigned d = (unsigned)__cvta_generic_to_shared(dst);
    asm volatile("cp.async.ca.shared.global [%0], [%1], 16, %2;"
                 :: "r"(d), "l"(src), "r"(srcsize));
}
#define CP_COMMIT() asm volatile("cp.async.commit_group;")
#define CP_WAIT(n)  asm volatile("cp.async.wait_group %0;" :: "n"(n))

__device__ __forceinline__ void gemm_load(long a_row_off, long b_off,
                                          int bm, int bn, int M, int kc,
                                          __nv_bfloat16* buf) {
    int t = threadIdx.x;
#pragma unroll
    for (int i = 0; i < 4; i++) {
        int id = t + i * 256;
        int j = id & 3, m = (id >> 2) & 127, pl = id >> 9;
        const __nv_bfloat16* srcA = pl ? g_al : g_ah;
        int gr = bm + m;
        cp16(buf + pl * PLANE + swoff(m, j),
             srcA + (a_row_off + gr) * 128 + kc + j * 8, (gr < M) ? 16 : 0);
    }
#pragma unroll
    for (int i = 0; i < 4; i++) {
        int id = t + i * 256;
        int j = id & 3, n = (id >> 2) & 127, pl = id >> 9;
        const __nv_bfloat16* srcB = pl ? g_wl : g_wh;
        cp16(buf + (2 + pl) * PLANE + swoff(n, j),
             srcB + b_off + (long)(bn + n) * 128 + kc + j * 8, 16);
    }
}

__device__ __forceinline__ void gemm_core(long a_row_off, long b_off,
                                          int bm, int bn, int M,
                                          __nv_bfloat16* smem,
                                          float acc[4][4][4]) {
    int lane = threadIdx.x & 31, wid = threadIdx.x >> 5;
    int wm = (wid & 1) * 64, wn = (wid >> 1) * 32;

#pragma unroll
    for (int a = 0; a < 4; a++)
#pragma unroll
        for (int b = 0; b < 4; b++)
#pragma unroll
            for (int c = 0; c < 4; c++) acc[a][b][c] = 0.f;

    gemm_load(a_row_off, b_off, bm, bn, M, 0, smem);
    CP_COMMIT();

    for (int ci = 0; ci < 4; ci++) {
        if (ci < 3) {
            gemm_load(a_row_off, b_off, bm, bn, M, (ci + 1) * 32,
                      smem + ((ci + 1) & 1) * 4 * PLANE);
            CP_COMMIT();
            CP_WAIT(1);
        } else {
            CP_WAIT(0);
        }
        __syncthreads();

        const __nv_bfloat16* buf = smem + (ci & 1) * 4 * PLANE;
        const __nv_bfloat16* sAh = buf;
        const __nv_bfloat16* sAl = buf + PLANE;
        const __nv_bfloat16* sBh = buf + 2 * PLANE;
        const __nv_bfloat16* sBl = buf + 3 * PLANE;

#pragma unroll
        for (int k16 = 0; k16 < 32; k16 += 16) {
            int jA = (k16 >> 3) + (lane >> 4);     // A chunk idx per lane
            int jB = (k16 >> 3) + ((lane >> 3) & 1);
            unsigned af[4][2][4];
            int arow = wm + (lane & 15);
#pragma unroll
            for (int mi = 0; mi < 4; mi++) {
                int r = arow + mi * 16;
                LDSM4(af[mi][0], (unsigned)__cvta_generic_to_shared(sAh + swoff(r, jA)));
                LDSM4(af[mi][1], (unsigned)__cvta_generic_to_shared(sAl + swoff(r, jA)));
            }
#pragma unroll
            for (int p = 0; p < 2; p++) {
                int nrow = wn + p * 16 + ((lane >> 4) & 1) * 8 + (lane & 7);
                unsigned bh[4], bl[4];
                LDSM4(bh, (unsigned)__cvta_generic_to_shared(sBh + swoff(nrow, jB)));
                LDSM4(bl, (unsigned)__cvta_generic_to_shared(sBl + swoff(nrow, jB)));
#pragma unroll
                for (int mi = 0; mi < 4; mi++) {
                    MMA16816(acc[mi][2 * p], af[mi][0][0], af[mi][0][1], af[mi][0][2], af[mi][0][3], bh[0], bh[1]);
                    MMA16816(acc[mi][2 * p], af[mi][0][0], af[mi][0][1], af[mi][0][2], af[mi][0][3], bl[0], bl[1]);
                    MMA16816(acc[mi][2 * p], af[mi][1][0], af[mi][1][1], af[mi][1][2], af[mi][1][3], bh[0], bh[1]);
                    MMA16816(acc[mi][2 * p + 1], af[mi][0][0], af[mi][0][1], af[mi][0][2], af[mi][0][3], bh[2], bh[3]);
                    MMA16816(acc[mi][2 * p + 1], af[mi][0][0], af[mi][0][1], af[mi][0][2], af[mi][0][3], bl[2], bl[3]);
                    MMA16816(acc[mi][2 * p + 1], af[mi][1][0], af[mi][1][1], af[mi][1][2], af[mi][1][3], bh[2], bh[3]);
                }
            }
        }
        __syncthreads();
    }
}

// combined qkv GEMM: one launch covers all 3 types
__global__ __launch_bounds__(256)
void mma_qkv_kernel(int l) {
    extern __shared__ __align__(16) __nv_bfloat16 smem[];
    int bid = blockIdx.x;
    int t, nt, mt;
    if (bid < QKV_B0)                { t = 0; nt = bid % 5; mt = bid / 5; }
    else if (bid < QKV_B0 + QKV_B1)  { t = 1; nt = 0; mt = bid - QKV_B0; }
    else { int b = bid - QKV_B0 - QKV_B1; t = 2; nt = b % 5; mt = b / 5; }

    int M = (t == 0) ? 50000 : (t == 1 ? 20000 : 10000);
    long offs = (t == 0) ? 0 : (t == 1 ? 50000 : 70000);
    long kroffA = (t == 0) ? 0 : 100000;
    long kroffB = (t == 0) ? 50000 : 110000;
    int bm = mt * 128, bn = nt * 128;
    int lt = l * NTYPE + t;

    float acc[4][4][4];
    gemm_core(offs, (long)lt * W2PER, bm, bn, M, smem, acc);

    int lane = threadIdx.x & 31, wid = threadIdx.x >> 5;
    int wm = (wid & 1) * 64, wn = (wid >> 1) * 32;
    const float* bias = g_b2 + (long)lt * 5 * FF;
#pragma unroll
    for (int mi = 0; mi < 4; mi++) {
#pragma unroll
        for (int nj = 0; nj < 4; nj++) {
            int rbase = bm + wm + mi * 16 + (lane >> 2);
            int col = bn + wn + nj * 8 + (lane & 3) * 2;
            float2 b2 = *(const float2*)&bias[col];
#pragma unroll
            for (int h = 0; h < 2; h++) {
                int gr = rbase + h * 8;
                if (gr >= M) continue;
                float o0 = acc[mi][nj][h * 2 + 0] + b2.x;
                float o1 = acc[mi][nj][h * 2 + 1] + b2.y;
                int seg = col >> 7, cc = col & 127;
                if (seg == 0) {
                    *(float2*)&g_q[(offs + gr) * 128 + cc] = make_float2(o0, o1);
                } else {
                    __half2 hv = __floats2half2_rn(o0, o1);
                    long roff = ((seg == 1 || seg == 3) ? kroffA : kroffB) + gr;
                    if (seg <= 2)
                        *(__half2*)&g_krh[roff * 128 + cc] = hv;
                    else
                        *(__half2*)&g_vrh[roff * 128 + cc] = hv;
                }
            }
        }
    }
}

// combined out GEMM: one launch covers all 3 types
__global__ __launch_bounds__(256)
void mma_out_kernel(int l, float* __restrict__ Cbase,
                    const float* __restrict__ Xbase,
                    const float* __restrict__ bout,
                    const float* __restrict__ skip, int xsplit) {
    extern __shared__ __align__(16) __nv_bfloat16 smem[];
    int bid = blockIdx.x;
    int t, mt;
    if (bid < MT0)            { t = 0; mt = bid; }
    else if (bid < MT0 + MT1) { t = 1; mt = bid - MT0; }
    else                      { t = 2; mt = bid - MT0 - MT1; }

    int M = (t == 0) ? 50000 : (t == 1 ? 20000 : 10000);
    long offs = (t == 0) ? 0 : (t == 1 ? 50000 : 70000);
    int bm = mt * 128;
    int lt = l * NTYPE + t;

    float acc[4][4][4];
    gemm_core(offs, (long)W2TOT + (long)lt * FF * FF, bm, 0, M, smem, acc);

    int lane = threadIdx.x & 31, wid = threadIdx.x >> 5;
    int wm = (wid & 1) * 64, wn = (wid >> 1) * 32;
    const float* bias = bout + (long)lt * FF;
    float sv = skip[lt];
    float s = 1.f / (1.f + expf(-sv));
    float oms = 1.f - s;
    float* C = Cbase + offs * FF;
    const float* X = Xbase + offs * FF;
#pragma unroll
    for (int mi = 0; mi < 4; mi++) {
#pragma unroll
        for (int nj = 0; nj < 4; nj++) {
            int rbase = bm + wm + mi * 16 + (lane >> 2);
            int col = wn + nj * 8 + (lane & 3) * 2;
            float2 b2 = *(const float2*)&bias[col];
#pragma unroll
            for (int h = 0; h < 2; h++) {
                int gr = rbase + h * 8;
                if (gr >= M) continue;
                float o0 = acc[mi][nj][h * 2 + 0] + b2.x;
                float o1 = acc[mi][nj][h * 2 + 1] + b2.y;
                float2 xv = *(const float2*)&X[(long)gr * 128 + col];
                float n0 = s * o0 + oms * xv.x;
                float n1 = s * o1 + oms * xv.y;
                float r0 = fmaxf(n0, 0.f) + xv.x;
                float r1 = fmaxf(n1, 0.f) + xv.y;
                *(float2*)&C[(long)gr * 128 + col] = make_float2(r0, r1);
                if (xsplit) {
                    long pidx = (offs + gr) * 128 + col;
                    __nv_bfloat16 h0 = __float2bfloat16_rn(r0);
                    __nv_bfloat16 h1 = __float2bfloat16_rn(r1);
                    __nv_bfloat16 l0 = __float2bfloat16_rn(r0 - __bfloat162float(h0));
                    __nv_bfloat16 l1 = __float2bfloat16_rn(r1 - __bfloat162float(h1));
                    __nv_bfloat162 hv; hv.x = h0; hv.y = h1;
                    __nv_bfloat162 lv; lv.x = l0; lv.y = l1;
                    *(__nv_bfloat162*)&g_ah[pidx] = hv;
                    *(__nv_bfloat162*)&g_al[pidx] = lv;
                }
            }
        }
    }
}

// ---------------- fused edge phase (head-per-lane) ----------------
__device__ __forceinline__ void unpack8(uint4 u, float* f) {
    float2 a = __half22float2(*(__half2*)&u.x);
    float2 b = __half22float2(*(__half2*)&u.y);
    float2 c = __half22float2(*(__half2*)&u.z);
    float2 d = __half22float2(*(__half2*)&u.w);
    f[0] = a.x; f[1] = a.y; f[2] = b.x; f[3] = b.y;
    f[4] = c.x; f[5] = c.y; f[6] = d.x; f[7] = d.y;
}

__global__ __launch_bounds__(256)
void edge_fused_kernel(const float* __restrict__ prel, int l) {
    int warp = (blockIdx.x * blockDim.x + threadIdx.x) >> 5;
    int lane = threadIdx.x & 31;
    if (warp >= NTOT) return;
    int g = lane >> 3;      // edge slot 0..3
    int h = lane & 7;       // head
    int o0 = g_off[warp], o1 = g_off[warp + 1];

    float q[16];
    const float4* qp = (const float4*)(g_q + (long)warp * FF + h * 16);
#pragma unroll
    for (int i = 0; i < 4; i++) *(float4*)&q[i * 4] = qp[i];

    float prh[NREL];
#pragma unroll
    for (int r = 0; r < NREL; r++)
        prh[r] = prel[(l * NREL + r) * HH + h] * 0.25f;

    float acc[16];
#pragma unroll
    for (int i = 0; i < 16; i++) acc[i] = 0.f;
    float denom = 0.f;

    for (int base = o0; base < o1; base += 4) {
        int j = base + g;
        bool act = (j < o1);
        int cv = act ? g_csr[j] : g_csr[base];
        long row = (long)(cv & 0xFFFFF) * FF + h * 16;
        int rel = cv >> 20;
        uint4 k0 = *(const uint4*)(g_krh + row);
        uint4 k1 = *(const uint4*)(g_krh + row + 8);
        uint4 v0 = *(const uint4*)(g_vrh + row);
        uint4 v1 = *(const uint4*)(g_vrh + row + 8);
        float kf[16];
        unpack8(k0, kf);
        unpack8(k1, kf + 8);
        float p = 0.f;
#pragma unroll
        for (int i = 0; i < 16; i++) p += q[i] * kf[i];
        float ex = act ? __expf(p * prh[rel]) : 0.f;
        float vf[16];
        unpack8(v0, vf);
        unpack8(v1, vf + 8);
#pragma unroll
        for (int i = 0; i < 16; i++) acc[i] += ex * vf[i];
        denom += ex;
    }

#pragma unroll
    for (int i = 0; i < 16; i++) {
        acc[i] += __shfl_xor_sync(0xFFFFFFFFu, acc[i], 8);
        acc[i] += __shfl_xor_sync(0xFFFFFFFFu, acc[i], 16);
    }
    denom += __shfl_xor_sync(0xFFFFFFFFu, denom, 8);
    denom += __shfl_xor_sync(0xFFFFFFFFu, denom, 16);

    if (g == 0) {
        float inv = (o1 > o0) ? 1.f / denom : 0.f;
        __nv_bfloat16 hb[16], lb[16];
#pragma unroll
        for (int i = 0; i < 16; i++) {
            float o = gelu_f(acc[i] * inv);
            hb[i] = __float2bfloat16_rn(o);
            lb[i] = __float2bfloat16_rn(o - __bfloat162float(hb[i]));
        }
        long idx = (long)warp * FF + h * 16;
        *(uint4*)&g_ah[idx]     = *(const uint4*)&hb[0];
        *(uint4*)&g_ah[idx + 8] = *(const uint4*)&hb[8];
        *(uint4*)&g_al[idx]     = *(const uint4*)&lb[0];
        *(uint4*)&g_al[idx + 8] = *(const uint4*)&lb[8];
    }
}

// ---------------- launch ----------------
extern "C" void kernel_launch(void* const* d_in, const int* in_sizes, int n_in,
                              void* d_out, int out_size) {
    const float* xg   = (const float*)d_in[0];
    const float* xd   = (const float*)d_in[1];
    const float* xr   = (const float*)d_in[2];
    const float* Wkqv = (const float*)d_in[3];
    const float* bkqv = (const float*)d_in[4];
    const float* Ak   = (const float*)d_in[5];
    const float* Av   = (const float*)d_in[6];
    const float* prel = (const float*)d_in[7];
    const float* Wout = (const float*)d_in[8];
    const float* bout = (const float*)d_in[9];
    const float* skip = (const float*)d_in[10];
    const int* e0 = (const int*)d_in[11];
    const int* e1 = (const int*)d_in[12];
    const int* e2 = (const int*)d_in[13];
    const int* e3 = (const int*)d_in[14];
    float* outp = (float*)d_out;

    const int SPLIT_BLOCKS = (NTOT * FF / 8 + 255) / 256;

    float* d_x0; cudaGetSymbolAddress((void**)&d_x0, g_x0);
    float* d_x1; cudaGetSymbolAddress((void**)&d_x1, g_x1);

    cudaFuncSetAttribute(mma_qkv_kernel, cudaFuncAttributeMaxDynamicSharedMemorySize, GEMM_SMEM);
    cudaFuncSetAttribute(mma_out_kernel, cudaFuncAttributeMaxDynamicSharedMemorySize, GEMM_SMEM);

    copyin_split_kernel<<<SPLIT_BLOCKS, 256>>>(xg, xd, xr);
    fold_kernel<<<(W2TOT + 255) / 256, 256>>>(Wkqv, Ak, Av);
    foldb_kernel<<<(NLAYER * NTYPE * 5 * FF + 255) / 256, 256>>>(bkqv, Ak, Av);
    splitw_kernel<<<(OUTW_ELEMS + 255) / 256, 256>>>(Wout);

    hist_all_kernel<<<(ETOT + 255) / 256, 256>>>(e0, e1, e2, e3);
    scan_kernel<<<1, 1024>>>();
    scatter_all_kernel<<<(ETOT + 255) / 256, 256>>>(e0, e1, e2, e3);

    for (int l = 0; l < NLAYER; l++) {
        mma_qkv_kernel<<<QKV_BLOCKS, 256, GEMM_SMEM>>>(l);
        edge_fused_kernel<<<NTOT / 8, 256>>>(prel, l);
        float* cdst = (l == 0) ? d_x1 : outp;
        const float* xcur = (l == 0) ? d_x0 : d_x1;
        mma_out_kernel<<<OUT_BLOCKS, 256, GEMM_SMEM>>>(
            l, cdst, xcur, bout, skip, (l == 0) ? 1 : 0);
    }
    (void)in_sizes; (void)n_in; (void)out_size;
}

// round 13
// speedup vs baseline: 1.6238x; 1.6238x over previous
#include <cuda_runtime.h>
#include <cuda_bf16.h>
#include <cuda_fp16.h>
#include <math.h>

// ---------------- problem constants ----------------
#define HH 8
#define DD 16
#define FF 128
#define F3 384
#define NLAYER 2
#define NTYPE 3
#define NREL 4
#define NTOT 80000
#define KRTOT 120000
#define ETOT 600000
#define BKPAD 40           // smem k-stride in bf16 (80 bytes): conflict-free ldmatrix
#define PLANE (128 * BKPAD)            // 5120 elems
#define GEMM_SMEM (2 * 4 * PLANE * 2)  // 80KB; 2 CTAs/SM (160KB of 228KB)

// folded qkv weights: [L][T][5 segs][128 n][128 k]
#define W2SEG 16384
#define W2PER (5 * W2SEG)
#define W2TOT (NLAYER * NTYPE * W2PER)          // 491520
#define OUTW_ELEMS (NLAYER * NTYPE * FF * FF)   //  98304
#define WALL (W2TOT + OUTW_ELEMS)

// block-mapping constants
#define MT0 391
#define MT1 157
#define MT2 79
#define QKV_B0 (5 * MT0)
#define QKV_B1 MT1
#define QKV_BLOCKS (QKV_B0 + QKV_B1 + 5 * MT2)   // 2507
#define OUT_BLOCKS (MT0 + MT1 + MT2)             // 627

// ---------------- device scratch ----------------
__device__ __align__(16) float g_x0[NTOT * FF];
__device__ __align__(16) float g_x1[NTOT * FF];
__device__ __align__(16) float g_q[NTOT * FF];
__device__ __align__(16) __half g_krh[KRTOT * FF];
__device__ __align__(16) __half g_vrh[KRTOT * FF];
__device__ __align__(16) __nv_bfloat16 g_ah[NTOT * FF];
__device__ __align__(16) __nv_bfloat16 g_al[NTOT * FF];
__device__ __align__(16) __nv_bfloat16 g_wh[WALL];
__device__ __align__(16) __nv_bfloat16 g_wl[WALL];
__device__ float g_b2[NLAYER * NTYPE * 5 * FF];
__device__ int g_deg[NTOT];
__device__ int g_off[NTOT + 1];
__device__ int g_cursor[NTOT];
__device__ int g_csr[ETOT];      // (r << 20) | (kroff + src)

__device__ __forceinline__ float gelu_f(float x) {
    return 0.5f * x * (1.f + erff(x * 0.70710678118654752440f));
}

// ---------------- setup kernels ----------------

__global__ void copyin_split_kernel(const float* __restrict__ xg,
                                    const float* __restrict__ xd,
                                    const float* __restrict__ xr) {
    int tid = blockIdx.x * blockDim.x + threadIdx.x;
    if (tid < NTOT) g_deg[tid] = 0;           // fused CSR-degree reset
    long i8 = (long)tid * 8;
    if (i8 >= (long)NTOT * FF) return;
    const long n1 = 50000L * FF, n2 = 70000L * FF;
    const float* src;
    long off;
    if (i8 < n1)      { src = xg; off = i8; }
    else if (i8 < n2) { src = xd; off = i8 - n1; }
    else              { src = xr; off = i8 - n2; }
    float v[8];
    *(float4*)&v[0] = *(const float4*)&src[off];
    *(float4*)&v[4] = *(const float4*)&src[off + 4];
    *(float4*)&g_x0[i8]     = *(const float4*)&v[0];
    *(float4*)&g_x0[i8 + 4] = *(const float4*)&v[4];
    __nv_bfloat16 h[8], l[8];
#pragma unroll
    for (int j = 0; j < 8; j++) {
        h[j] = __float2bfloat16_rn(v[j]);
        l[j] = __float2bfloat16_rn(v[j] - __bfloat162float(h[j]));
    }
    *(uint4*)&g_ah[i8] = *(const uint4*)&h[0];
    *(uint4*)&g_al[i8] = *(const uint4*)&l[0];
}

__global__ void fold_kernel(const float* __restrict__ Wkqv,
                            const float* __restrict__ Ak,
                            const float* __restrict__ Av) {
    int idx = blockIdx.x * blockDim.x + threadIdx.x;
    if (idx >= W2TOT) return;
    int k = idx & 127;
    int n = (idx >> 7) & 127;
    int sl = idx >> 14;
    int seg = sl % 5, lt = sl / 5;
    int l = lt / NTYPE, t = lt % NTYPE;
    const float* W = Wkqv + (long)lt * FF * F3;
    float val = 0.f;
    if (seg == 0) {
        val = W[(long)k * F3 + FF + n];
    } else if (t != 1) {
        int r = (t == 0 ? 0 : 2) + ((seg == 2 || seg == 4) ? 1 : 0);
        int h = n >> 4, e = n & 15;
        const float* A = ((seg <= 2) ? Ak : Av) +
                         ((long)(l * NREL + r) * HH + h) * DD * DD;
        int colbase = (seg <= 2 ? 0 : 2 * FF) + h * DD;
#pragma unroll
        for (int d = 0; d < DD; d++)
            val += W[(long)k * F3 + colbase + d] * A[d * DD + e];
    }
    __nv_bfloat16 hi = __float2bfloat16_rn(val);
    g_wh[idx] = hi;
    g_wl[idx] = __float2bfloat16_rn(val - __bfloat162float(hi));
}

__global__ void foldb_kernel(const float* __restrict__ bkqv,
                             const float* __restrict__ Ak,
                             const float* __restrict__ Av) {
    int idx = blockIdx.x * blockDim.x + threadIdx.x;
    if (idx >= NLAYER * NTYPE * 5 * FF) return;
    int n = idx & 127;
    int sl = idx >> 7;
    int seg = sl % 5, lt = sl / 5;
    int l = lt / NTYPE, t = lt % NTYPE;
    const float* b = bkqv + (long)lt * F3;
    float val = 0.f;
    if (seg == 0) {
        val = b[FF + n];
    } else if (t != 1) {
        int r = (t == 0 ? 0 : 2) + ((seg == 2 || seg == 4) ? 1 : 0);
        int h = n >> 4, e = n & 15;
        const float* A = ((seg <= 2) ? Ak : Av) +
                         ((long)(l * NREL + r) * HH + h) * DD * DD;
        int colbase = (seg <= 2 ? 0 : 2 * FF) + h * DD;
#pragma unroll
        for (int d = 0; d < DD; d++)
            val += b[colbase + d] * A[d * DD + e];
    }
    g_b2[idx] = val;
}

__global__ void splitw_kernel(const float* __restrict__ Wout) {
    int idx = blockIdx.x * blockDim.x + threadIdx.x;
    if (idx >= OUTW_ELEMS) return;
    int lt = idx / (FF * FF);
    int rem = idx - lt * (FF * FF);
    int n = rem / FF, k = rem % FF;
    float val = Wout[(long)lt * FF * FF + (long)k * FF + n];
    __nv_bfloat16 hi = __float2bfloat16_rn(val);
    g_wh[W2TOT + idx] = hi;
    g_wl[W2TOT + idx] = __float2bfloat16_rn(val - __bfloat162float(hi));
}

// ---------------- CSR build ----------------

__device__ __forceinline__ void edge_decode(int e, const int* e0, const int* e1,
                                            const int* e2, const int* e3,
                                            int& r, int& off, const int*& ep,
                                            int& E, int& dt_off, int& kroff) {
    if (e < 300000)      { r = 0; off = e;          ep = e0; E = 300000; dt_off = 0;     kroff = 0; }
    else if (e < 450000) { r = 1; off = e - 300000; ep = e1; E = 150000; dt_off = 50000; kroff = 50000; }
    else if (e < 550000) { r = 2; off = e - 450000; ep = e2; E = 100000; dt_off = 0;     kroff = 100000; }
    else                 { r = 3; off = e - 550000; ep = e3; E = 50000;  dt_off = 50000; kroff = 110000; }
}

__global__ void hist_all_kernel(const int* __restrict__ e0, const int* __restrict__ e1,
                                const int* __restrict__ e2, const int* __restrict__ e3) {
    int e = blockIdx.x * blockDim.x + threadIdx.x;
    if (e >= ETOT) return;
    int r, off, E, dt_off, kroff;
    const int* ep;
    edge_decode(e, e0, e1, e2, e3, r, off, ep, E, dt_off, kroff);
    atomicAdd(&g_deg[dt_off + ep[E + off]], 1);
}

__global__ void scan_kernel() {
    __shared__ int s[1024];
    int t = threadIdx.x;
    const int CHUNK = 79;
    int base = t * CHUNK;
    int sum = 0;
    for (int i = 0; i < CHUNK; i++) {
        int idx = base + i;
        if (idx < NTOT) sum += g_deg[idx];
    }
    s[t] = sum;
    __syncthreads();
    for (int d = 1; d < 1024; d <<= 1) {
        int v = (t >= d) ? s[t - d] : 0;
        __syncthreads();
        s[t] += v;
        __syncthreads();
    }
    int run = (t == 0) ? 0 : s[t - 1];
    for (int i = 0; i < CHUNK; i++) {
        int idx = base + i;
        if (idx < NTOT) {
            g_off[idx] = run;
            g_cursor[idx] = run;
            run += g_deg[idx];
        }
    }
    if (t == 0) g_off[NTOT] = ETOT;
}

__global__ void scatter_all_kernel(const int* __restrict__ e0, const int* __restrict__ e1,
                                   const int* __restrict__ e2, const int* __restrict__ e3) {
    int e = blockIdx.x * blockDim.x + threadIdx.x;
    if (e >= ETOT) return;
    int r, off, E, dt_off, kroff;
    const int* ep;
    edge_decode(e, e0, e1, e2, e3, r, off, ep, E, dt_off, kroff);
    int pos = atomicAdd(&g_cursor[dt_off + ep[E + off]], 1);
    g_csr[pos] = (r << 20) | (kroff + ep[off]);
}

// ---------------- tensor-core GEMM core ----------------
#define LDSM4(r, addr) \
    asm volatile("ldmatrix.sync.aligned.m8n8.x4.shared.b16 {%0,%1,%2,%3}, [%4];" \
        : "=r"((r)[0]), "=r"((r)[1]), "=r"((r)[2]), "=r"((r)[3]) : "r"(addr))

#define MMA16816(c, a0, a1, a2, a3, b0, b1) \
    asm volatile("mma.sync.aligned.m16n8k16.row.col.f32.bf16.bf16.f32 " \
        "{%0,%1,%2,%3}, {%4,%5,%6,%7}, {%8,%9}, {%0,%1,%2,%3};" \
        : "+f"((c)[0]), "+f"((c)[1]), "+f"((c)[2]), "+f"((c)[3]) \
        : "r"(a0), "r"(a1), "r"(a2), "r"(a3), "r"(b0), "r"(b1))

__device__ __forceinline__ void cp16(__nv_bfloat16* dst, const __nv_bfloat16* src,
                                     int srcsize) {
    unsigned d = (unsigned)__cvta_generic_to_shared(dst);
    asm volatile("cp.async.cg.shared.global [%0], [%1], 16, %2;"
                 :: "r"(d), "l"(src), "r"(srcsize));
}
#define CP_COMMIT() asm volatile("cp.async.commit_group;")
#define CP_WAIT(n)  asm volatile("cp.async.wait_group %0;" :: "n"(n))

__device__ __forceinline__ void gemm_core(long a_row_off, long b_off,
                                          int bm, int bn, int M,
                                          __nv_bfloat16* smem,
                                          float acc[4][4][4]) {
    int t = threadIdx.x;
    int lane = t & 31, wid = t >> 5;
    int wm = (wid & 1) * 64, wn = (wid >> 1) * 32;

#pragma unroll
    for (int a = 0; a < 4; a++)
#pragma unroll
        for (int b = 0; b < 4; b++)
#pragma unroll
            for (int c = 0; c < 4; c++) acc[a][b][c] = 0.f;

    // initial load, chunk 0
#pragma unroll
    for (int i = 0; i < 4; i++) {
        int id = t + i * 256;
        int j = id & 3, m = (id >> 2) & 127, pl = id >> 9;
        const __nv_bfloat16* srcA = pl ? g_al : g_ah;
        int gr = bm + m;
        cp16(smem + pl * PLANE + m * BKPAD + j * 8,
             srcA + (a_row_off + gr) * 128 + j * 8, (gr < M) ? 16 : 0);
    }
#pragma unroll
    for (int i = 0; i < 4; i++) {
        int id = t + i * 256;
        int j = id & 3, n = (id >> 2) & 127, pl = id >> 9;
        const __nv_bfloat16* srcB = pl ? g_wl : g_wh;
        cp16(smem + (2 + pl) * PLANE + n * BKPAD + j * 8,
             srcB + b_off + (long)(bn + n) * 128 + j * 8, 16);
    }
    CP_COMMIT();

    for (int ci = 0; ci < 4; ci++) {
        if (ci < 3) {
            int kc = (ci + 1) * 32;
            __nv_bfloat16* nb = smem + ((ci + 1) & 1) * 4 * PLANE;
#pragma unroll
            for (int i = 0; i < 4; i++) {
                int id = t + i * 256;
                int j = id & 3, m = (id >> 2) & 127, pl = id >> 9;
                const __nv_bfloat16* srcA = pl ? g_al : g_ah;
                int gr = bm + m;
                cp16(nb + pl * PLANE + m * BKPAD + j * 8,
                     srcA + (a_row_off + gr) * 128 + kc + j * 8, (gr < M) ? 16 : 0);
            }
#pragma unroll
            for (int i = 0; i < 4; i++) {
                int id = t + i * 256;
                int j = id & 3, n = (id >> 2) & 127, pl = id >> 9;
                const __nv_bfloat16* srcB = pl ? g_wl : g_wh;
                cp16(nb + (2 + pl) * PLANE + n * BKPAD + j * 8,
                     srcB + b_off + (long)(bn + n) * 128 + kc + j * 8, 16);
            }
            CP_COMMIT();
            CP_WAIT(1);
        } else {
            CP_WAIT(0);
        }
        __syncthreads();

        const __nv_bfloat16* buf = smem + (ci & 1) * 4 * PLANE;
        const __nv_bfloat16* sAh = buf;
        const __nv_bfloat16* sAl = buf + PLANE;
        const __nv_bfloat16* sBh = buf + 2 * PLANE;
        const __nv_bfloat16* sBl = buf + 3 * PLANE;

#pragma unroll
        for (int k16 = 0; k16 < 32; k16 += 16) {
            unsigned af[4][2][4];
            int arow = wm + (lane & 15);
            int akoff = k16 + (lane >> 4) * 8;
#pragma unroll
            for (int mi = 0; mi < 4; mi++) {
                unsigned ah = (unsigned)__cvta_generic_to_shared(
                    sAh + (arow + mi * 16) * BKPAD + akoff);
                unsigned al = (unsigned)__cvta_generic_to_shared(
                    sAl + (arow + mi * 16) * BKPAD + akoff);
                LDSM4(af[mi][0], ah);
                LDSM4(af[mi][1], al);
            }
#pragma unroll
            for (int p = 0; p < 2; p++) {
                int nrow = wn + p * 16 + ((lane >> 4) & 1) * 8 + (lane & 7);
                int bkoff = k16 + ((lane >> 3) & 1) * 8;
                unsigned bh[4], bl[4];
                LDSM4(bh, (unsigned)__cvta_generic_to_shared(sBh + nrow * BKPAD + bkoff));
                LDSM4(bl, (unsigned)__cvta_generic_to_shared(sBl + nrow * BKPAD + bkoff));
#pragma unroll
                for (int mi = 0; mi < 4; mi++) {
                    MMA16816(acc[mi][2 * p], af[mi][0][0], af[mi][0][1], af[mi][0][2], af[mi][0][3], bh[0], bh[1]);
                    MMA16816(acc[mi][2 * p], af[mi][0][0], af[mi][0][1], af[mi][0][2], af[mi][0][3], bl[0], bl[1]);
                    MMA16816(acc[mi][2 * p], af[mi][1][0], af[mi][1][1], af[mi][1][2], af[mi][1][3], bh[0], bh[1]);
                    MMA16816(acc[mi][2 * p + 1], af[mi][0][0], af[mi][0][1], af[mi][0][2], af[mi][0][3], bh[2], bh[3]);
                    MMA16816(acc[mi][2 * p + 1], af[mi][0][0], af[mi][0][1], af[mi][0][2], af[mi][0][3], bl[2], bl[3]);
                    MMA16816(acc[mi][2 * p + 1], af[mi][1][0], af[mi][1][1], af[mi][1][2], af[mi][1][3], bh[2], bh[3]);
                }
            }
        }
        __syncthreads();
    }
}

// combined qkv GEMM: one launch covers all 3 types
__global__ __launch_bounds__(256)
void mma_qkv_kernel(int l) {
    extern __shared__ __align__(16) __nv_bfloat16 smem[];
    int bid = blockIdx.x;
    int t, nt, mt;
    if (bid < QKV_B0)                { t = 0; nt = bid % 5; mt = bid / 5; }
    else if (bid < QKV_B0 + QKV_B1)  { t = 1; nt = 0; mt = bid - QKV_B0; }
    else { int b = bid - QKV_B0 - QKV_B1; t = 2; nt = b % 5; mt = b / 5; }

    int M = (t == 0) ? 50000 : (t == 1 ? 20000 : 10000);
    long offs = (t == 0) ? 0 : (t == 1 ? 50000 : 70000);
    long kroffA = (t == 0) ? 0 : 100000;
    long kroffB = (t == 0) ? 50000 : 110000;
    int bm = mt * 128, bn = nt * 128;
    int lt = l * NTYPE + t;

    float acc[4][4][4];
    gemm_core(offs, (long)lt * W2PER, bm, bn, M, smem, acc);

    int lane = threadIdx.x & 31, wid = threadIdx.x >> 5;
    int wm = (wid & 1) * 64, wn = (wid >> 1) * 32;
    const float* bias = g_b2 + (long)lt * 5 * FF;
#pragma unroll
    for (int mi = 0; mi < 4; mi++) {
#pragma unroll
        for (int nj = 0; nj < 4; nj++) {
            int rbase = bm + wm + mi * 16 + (lane >> 2);
            int col = bn + wn + nj * 8 + (lane & 3) * 2;
            float2 b2 = *(const float2*)&bias[col];
#pragma unroll
            for (int h = 0; h < 2; h++) {
                int gr = rbase + h * 8;
                if (gr >= M) continue;
                float o0 = acc[mi][nj][h * 2 + 0] + b2.x;
                float o1 = acc[mi][nj][h * 2 + 1] + b2.y;
                int seg = col >> 7, cc = col & 127;
                if (seg == 0) {
                    *(float2*)&g_q[(offs + gr) * 128 + cc] = make_float2(o0, o1);
                } else {
                    __half2 hv = __floats2half2_rn(o0, o1);
                    long roff = ((seg == 1 || seg == 3) ? kroffA : kroffB) + gr;
                    if (seg <= 2)
                        *(__half2*)&g_krh[roff * 128 + cc] = hv;
                    else
                        *(__half2*)&g_vrh[roff * 128 + cc] = hv;
                }
            }
        }
    }
}

// combined out GEMM: one launch covers all 3 types
__global__ __launch_bounds__(256)
void mma_out_kernel(int l, float* __restrict__ Cbase,
                    const float* __restrict__ Xbase,
                    const float* __restrict__ bout,
                    const float* __restrict__ skip, int xsplit) {
    extern __shared__ __align__(16) __nv_bfloat16 smem[];
    int bid = blockIdx.x;
    int t, mt;
    if (bid < MT0)            { t = 0; mt = bid; }
    else if (bid < MT0 + MT1) { t = 1; mt = bid - MT0; }
    else                      { t = 2; mt = bid - MT0 - MT1; }

    int M = (t == 0) ? 50000 : (t == 1 ? 20000 : 10000);
    long offs = (t == 0) ? 0 : (t == 1 ? 50000 : 70000);
    int bm = mt * 128;
    int lt = l * NTYPE + t;

    float acc[4][4][4];
    gemm_core(offs, (long)W2TOT + (long)lt * FF * FF, bm, 0, M, smem, acc);

    int lane = threadIdx.x & 31, wid = threadIdx.x >> 5;
    int wm = (wid & 1) * 64, wn = (wid >> 1) * 32;
    const float* bias = bout + (long)lt * FF;
    float sv = skip[lt];
    float s = 1.f / (1.f + expf(-sv));
    float oms = 1.f - s;
    float* C = Cbase + offs * FF;
    const float* X = Xbase + offs * FF;
#pragma unroll
    for (int mi = 0; mi < 4; mi++) {
#pragma unroll
        for (int nj = 0; nj < 4; nj++) {
            int rbase = bm + wm + mi * 16 + (lane >> 2);
            int col = wn + nj * 8 + (lane & 3) * 2;
            float2 b2 = *(const float2*)&bias[col];
#pragma unroll
            for (int h = 0; h < 2; h++) {
                int gr = rbase + h * 8;
                if (gr >= M) continue;
                float o0 = acc[mi][nj][h * 2 + 0] + b2.x;
                float o1 = acc[mi][nj][h * 2 + 1] + b2.y;
                float2 xv = *(const float2*)&X[(long)gr * 128 + col];
                float n0 = s * o0 + oms * xv.x;
                float n1 = s * o1 + oms * xv.y;
                float r0 = fmaxf(n0, 0.f) + xv.x;
                float r1 = fmaxf(n1, 0.f) + xv.y;
                *(float2*)&C[(long)gr * 128 + col] = make_float2(r0, r1);
                if (xsplit) {
                    long pidx = (offs + gr) * 128 + col;
                    __nv_bfloat16 h0 = __float2bfloat16_rn(r0);
                    __nv_bfloat16 h1 = __float2bfloat16_rn(r1);
                    __nv_bfloat16 l0 = __float2bfloat16_rn(r0 - __bfloat162float(h0));
                    __nv_bfloat16 l1 = __float2bfloat16_rn(r1 - __bfloat162float(h1));
                    __nv_bfloat162 hv; hv.x = h0; hv.y = h1;
                    __nv_bfloat162 lv; lv.x = l0; lv.y = l1;
                    *(__nv_bfloat162*)&g_ah[pidx] = hv;
                    *(__nv_bfloat162*)&g_al[pidx] = lv;
                }
            }
        }
    }
}

// ---------------- fused edge phase (head-per-lane) ----------------
__device__ __forceinline__ void unpack8(uint4 u, float* f) {
    float2 a = __half22float2(*(__half2*)&u.x);
    float2 b = __half22float2(*(__half2*)&u.y);
    float2 c = __half22float2(*(__half2*)&u.z);
    float2 d = __half22float2(*(__half2*)&u.w);
    f[0] = a.x; f[1] = a.y; f[2] = b.x; f[3] = b.y;
    f[4] = c.x; f[5] = c.y; f[6] = d.x; f[7] = d.y;
}

__global__ __launch_bounds__(256)
void edge_fused_kernel(const float* __restrict__ prel, int l) {
    int warp = (blockIdx.x * blockDim.x + threadIdx.x) >> 5;
    int lane = threadIdx.x & 31;
    if (warp >= NTOT) return;
    int g = lane >> 3;      // edge slot 0..3
    int h = lane & 7;       // head
    int o0 = g_off[warp], o1 = g_off[warp + 1];

    float q[16];
    const float4* qp = (const float4*)(g_q + (long)warp * FF + h * 16);
#pragma unroll
    for (int i = 0; i < 4; i++) *(float4*)&q[i * 4] = qp[i];

    float prh[NREL];
#pragma unroll
    for (int r = 0; r < NREL; r++)
        prh[r] = prel[(l * NREL + r) * HH + h] * 0.25f;

    float acc[16];
#pragma unroll
    for (int i = 0; i < 16; i++) acc[i] = 0.f;
    float denom = 0.f;

    for (int base = o0; base < o1; base += 4) {
        int j = base + g;
        bool act = (j < o1);
        int cv = act ? g_csr[j] : g_csr[base];
        long row = (long)(cv & 0xFFFFF) * FF + h * 16;
        int rel = cv >> 20;
        uint4 k0 = *(const uint4*)(g_krh + row);
        uint4 k1 = *(const uint4*)(g_krh + row + 8);
        uint4 v0 = *(const uint4*)(g_vrh + row);
        uint4 v1 = *(const uint4*)(g_vrh + row + 8);
        float kf[16];
        unpack8(k0, kf);
        unpack8(k1, kf + 8);
        float p = 0.f;
#pragma unroll
        for (int i = 0; i < 16; i++) p += q[i] * kf[i];
        float ex = act ? __expf(p * prh[rel]) : 0.f;
        float vf[16];
        unpack8(v0, vf);
        unpack8(v1, vf + 8);
#pragma unroll
        for (int i = 0; i < 16; i++) acc[i] += ex * vf[i];
        denom += ex;
    }

#pragma unroll
    for (int i = 0; i < 16; i++) {
        acc[i] += __shfl_xor_sync(0xFFFFFFFFu, acc[i], 8);
        acc[i] += __shfl_xor_sync(0xFFFFFFFFu, acc[i], 16);
    }
    denom += __shfl_xor_sync(0xFFFFFFFFu, denom, 8);
    denom += __shfl_xor_sync(0xFFFFFFFFu, denom, 16);

    if (g == 0) {
        float inv = (o1 > o0) ? 1.f / denom : 0.f;
        __nv_bfloat16 hb[16], lb[16];
#pragma unroll
        for (int i = 0; i < 16; i++) {
            float o = gelu_f(acc[i] * inv);
            hb[i] = __float2bfloat16_rn(o);
            lb[i] = __float2bfloat16_rn(o - __bfloat162float(hb[i]));
        }
        long idx = (long)warp * FF + h * 16;
        *(uint4*)&g_ah[idx]     = *(const uint4*)&hb[0];
        *(uint4*)&g_ah[idx + 8] = *(const uint4*)&hb[8];
        *(uint4*)&g_al[idx]     = *(const uint4*)&lb[0];
        *(uint4*)&g_al[idx + 8] = *(const uint4*)&lb[8];
    }
}

// ---------------- launch ----------------
extern "C" void kernel_launch(void* const* d_in, const int* in_sizes, int n_in,
                              void* d_out, int out_size) {
    const float* xg   = (const float*)d_in[0];
    const float* xd   = (const float*)d_in[1];
    const float* xr   = (const float*)d_in[2];
    const float* Wkqv = (const float*)d_in[3];
    const float* bkqv = (const float*)d_in[4];
    const float* Ak   = (const float*)d_in[5];
    const float* Av   = (const float*)d_in[6];
    const float* prel = (const float*)d_in[7];
    const float* Wout = (const float*)d_in[8];
    const float* bout = (const float*)d_in[9];
    const float* skip = (const float*)d_in[10];
    const int* e0 = (const int*)d_in[11];
    const int* e1 = (const int*)d_in[12];
    const int* e2 = (const int*)d_in[13];
    const int* e3 = (const int*)d_in[14];
    float* outp = (float*)d_out;

    const int SPLIT_BLOCKS = (NTOT * FF / 8 + 255) / 256;

    float* d_x0; cudaGetSymbolAddress((void**)&d_x0, g_x0);
    float* d_x1; cudaGetSymbolAddress((void**)&d_x1, g_x1);

    cudaFuncSetAttribute(mma_qkv_kernel, cudaFuncAttributeMaxDynamicSharedMemorySize, GEMM_SMEM);
    cudaFuncSetAttribute(mma_out_kernel, cudaFuncAttributeMaxDynamicSharedMemorySize, GEMM_SMEM);

    copyin_split_kernel<<<SPLIT_BLOCKS, 256>>>(xg, xd, xr);
    fold_kernel<<<(W2TOT + 255) / 256, 256>>>(Wkqv, Ak, Av);
    foldb_kernel<<<(NLAYER * NTYPE * 5 * FF + 255) / 256, 256>>>(bkqv, Ak, Av);
    splitw_kernel<<<(OUTW_ELEMS + 255) / 256, 256>>>(Wout);

    hist_all_kernel<<<(ETOT + 255) / 256, 256>>>(e0, e1, e2, e3);
    scan_kernel<<<1, 1024>>>();
    scatter_all_kernel<<<(ETOT + 255) / 256, 256>>>(e0, e1, e2, e3);

    for (int l = 0; l < NLAYER; l++) {
        mma_qkv_kernel<<<QKV_BLOCKS, 256, GEMM_SMEM>>>(l);
        edge_fused_kernel<<<NTOT / 8, 256>>>(prel, l);
        float* cdst = (l == 0) ? d_x1 : outp;
        const float* xcur = (l == 0) ? d_x0 : d_x1;
        mma_out_kernel<<<OUT_BLOCKS, 256, GEMM_SMEM>>>(
            l, cdst, xcur, bout, skip, (l == 0) ? 1 : 0);
    }
    (void)in_sizes; (void)n_in; (void)out_size;
}

// round 14
// speedup vs baseline: 1.9061x; 1.1738x over previous
#include <cuda_runtime.h>
#include <cuda_bf16.h>
#include <cuda_fp16.h>
#include <math.h>

// ---------------- problem constants ----------------
#define HH 8
#define DD 16
#define FF 128
#define F3 384
#define NLAYER 2
#define NTYPE 3
#define NREL 4
#define NTOT 80000
#define KRTOT 120000
#define ETOT 600000
#define BKPAD 40           // smem k-stride in bf16 (80 bytes): conflict-free ldmatrix
#define PLANE (128 * BKPAD)            // 5120 elems
#define GEMM_SMEM (2 * 4 * PLANE * 2)  // 80KB; 2 CTAs/SM (160KB of 228KB)

// folded qkv weights: [L][T][5 segs][128 n][128 k]
#define W2SEG 16384
#define W2PER (5 * W2SEG)
#define W2TOT (NLAYER * NTYPE * W2PER)          // 491520
#define OUTW_ELEMS (NLAYER * NTYPE * FF * FF)   //  98304
#define WALL (W2TOT + OUTW_ELEMS)

// block-mapping constants
#define MT0 391
#define MT1 157
#define MT2 79
#define QKV_B0 (5 * MT0)
#define QKV_B1 MT1
#define QKV_BLOCKS (QKV_B0 + QKV_B1 + 5 * MT2)   // 2507
#define OUT_BLOCKS (MT0 + MT1 + MT2)             // 627

// ---------------- device scratch ----------------
__device__ __align__(16) float g_x0[NTOT * FF];
__device__ __align__(16) float g_x1[NTOT * FF];
__device__ __align__(16) float g_q[NTOT * FF];
__device__ __align__(16) __half g_krh[KRTOT * FF];
__device__ __align__(16) __half g_vrh[KRTOT * FF];
__device__ __align__(16) __nv_bfloat16 g_ah[NTOT * FF];
__device__ __align__(16) __nv_bfloat16 g_al[NTOT * FF];
__device__ __align__(16) __nv_bfloat16 g_wh[WALL];
__device__ __align__(16) __nv_bfloat16 g_wl[WALL];
__device__ float g_b2[NLAYER * NTYPE * 5 * FF];
__device__ int g_deg[NTOT];
__device__ int g_off[NTOT + 1];
__device__ int g_cursor[NTOT];
__device__ int g_csr[ETOT];      // (r << 20) | (kroff + src)

__device__ __forceinline__ float gelu_f(float x) {
    return 0.5f * x * (1.f + erff(x * 0.70710678118654752440f));
}

// ---------------- setup kernels ----------------

__global__ void copyin_split_kernel(const float* __restrict__ xg,
                                    const float* __restrict__ xd,
                                    const float* __restrict__ xr) {
    int tid = blockIdx.x * blockDim.x + threadIdx.x;
    long i8 = (long)tid * 8;
    if (i8 >= (long)NTOT * FF) return;
    const long n1 = 50000L * FF, n2 = 70000L * FF;
    const float* src;
    long off;
    if (i8 < n1)      { src = xg; off = i8; }
    else if (i8 < n2) { src = xd; off = i8 - n1; }
    else              { src = xr; off = i8 - n2; }
    float v[8];
    *(float4*)&v[0] = *(const float4*)&src[off];
    *(float4*)&v[4] = *(const float4*)&src[off + 4];
    *(float4*)&g_x0[i8]     = *(const float4*)&v[0];
    *(float4*)&g_x0[i8 + 4] = *(const float4*)&v[4];
    __nv_bfloat16 h[8], l[8];
#pragma unroll
    for (int j = 0; j < 8; j++) {
        h[j] = __float2bfloat16_rn(v[j]);
        l[j] = __float2bfloat16_rn(v[j] - __bfloat162float(h[j]));
    }
    *(uint4*)&g_ah[i8] = *(const uint4*)&h[0];
    *(uint4*)&g_al[i8] = *(const uint4*)&l[0];
}

__global__ void fold_kernel(const float* __restrict__ Wkqv,
                            const float* __restrict__ Ak,
                            const float* __restrict__ Av) {
    int idx = blockIdx.x * blockDim.x + threadIdx.x;
    if (idx >= W2TOT) return;
    int k = idx & 127;
    int n = (idx >> 7) & 127;
    int sl = idx >> 14;
    int seg = sl % 5, lt = sl / 5;
    int l = lt / NTYPE, t = lt % NTYPE;
    const float* W = Wkqv + (long)lt * FF * F3;
    float val = 0.f;
    if (seg == 0) {
        val = W[(long)k * F3 + FF + n];
    } else if (t != 1) {
        int r = (t == 0 ? 0 : 2) + ((seg == 2 || seg == 4) ? 1 : 0);
        int h = n >> 4, e = n & 15;
        const float* A = ((seg <= 2) ? Ak : Av) +
                         ((long)(l * NREL + r) * HH + h) * DD * DD;
        int colbase = (seg <= 2 ? 0 : 2 * FF) + h * DD;
#pragma unroll
        for (int d = 0; d < DD; d++)
            val += W[(long)k * F3 + colbase + d] * A[d * DD + e];
    }
    __nv_bfloat16 hi = __float2bfloat16_rn(val);
    g_wh[idx] = hi;
    g_wl[idx] = __float2bfloat16_rn(val - __bfloat162float(hi));
}

__global__ void foldb_kernel(const float* __restrict__ bkqv,
                             const float* __restrict__ Ak,
                             const float* __restrict__ Av) {
    int idx = blockIdx.x * blockDim.x + threadIdx.x;
    if (idx >= NLAYER * NTYPE * 5 * FF) return;
    int n = idx & 127;
    int sl = idx >> 7;
    int seg = sl % 5, lt = sl / 5;
    int l = lt / NTYPE, t = lt % NTYPE;
    const float* b = bkqv + (long)lt * F3;
    float val = 0.f;
    if (seg == 0) {
        val = b[FF + n];
    } else if (t != 1) {
        int r = (t == 0 ? 0 : 2) + ((seg == 2 || seg == 4) ? 1 : 0);
        int h = n >> 4, e = n & 15;
        const float* A = ((seg <= 2) ? Ak : Av) +
                         ((long)(l * NREL + r) * HH + h) * DD * DD;
        int colbase = (seg <= 2 ? 0 : 2 * FF) + h * DD;
#pragma unroll
        for (int d = 0; d < DD; d++)
            val += b[colbase + d] * A[d * DD + e];
    }
    g_b2[idx] = val;
}

__global__ void splitw_kernel(const float* __restrict__ Wout) {
    int idx = blockIdx.x * blockDim.x + threadIdx.x;
    if (idx >= OUTW_ELEMS) return;
    int lt = idx / (FF * FF);
    int rem = idx - lt * (FF * FF);
    int n = rem / FF, k = rem % FF;
    float val = Wout[(long)lt * FF * FF + (long)k * FF + n];
    __nv_bfloat16 hi = __float2bfloat16_rn(val);
    g_wh[W2TOT + idx] = hi;
    g_wl[W2TOT + idx] = __float2bfloat16_rn(val - __bfloat162float(hi));
}

// ---------------- CSR build ----------------

__global__ void zero_deg_kernel() {
    int i = blockIdx.x * blockDim.x + threadIdx.x;
    if (i < NTOT) g_deg[i] = 0;
}

__device__ __forceinline__ void edge_decode(int e, const int* e0, const int* e1,
                                            const int* e2, const int* e3,
                                            int& r, int& off, const int*& ep,
                                            int& E, int& dt_off, int& kroff) {
    if (e < 300000)      { r = 0; off = e;          ep = e0; E = 300000; dt_off = 0;     kroff = 0; }
    else if (e < 450000) { r = 1; off = e - 300000; ep = e1; E = 150000; dt_off = 50000; kroff = 50000; }
    else if (e < 550000) { r = 2; off = e - 450000; ep = e2; E = 100000; dt_off = 0;     kroff = 100000; }
    else                 { r = 3; off = e - 550000; ep = e3; E = 50000;  dt_off = 50000; kroff = 110000; }
}

__global__ void hist_all_kernel(const int* __restrict__ e0, const int* __restrict__ e1,
                                const int* __restrict__ e2, const int* __restrict__ e3) {
    int e = blockIdx.x * blockDim.x + threadIdx.x;
    if (e >= ETOT) return;
    int r, off, E, dt_off, kroff;
    const int* ep;
    edge_decode(e, e0, e1, e2, e3, r, off, ep, E, dt_off, kroff);
    atomicAdd(&g_deg[dt_off + ep[E + off]], 1);
}

__global__ void scan_kernel() {
    __shared__ int s[1024];
    int t = threadIdx.x;
    const int CHUNK = 79;
    int base = t * CHUNK;
    int sum = 0;
    for (int i = 0; i < CHUNK; i++) {
        int idx = base + i;
        if (idx < NTOT) sum += g_deg[idx];
    }
    s[t] = sum;
    __syncthreads();
    for (int d = 1; d < 1024; d <<= 1) {
        int v = (t >= d) ? s[t - d] : 0;
        __syncthreads();
        s[t] += v;
        __syncthreads();
    }
    int run = (t == 0) ? 0 : s[t - 1];
    for (int i = 0; i < CHUNK; i++) {
        int idx = base + i;
        if (idx < NTOT) {
            g_off[idx] = run;
            g_cursor[idx] = run;
            run += g_deg[idx];
        }
    }
    if (t == 0) g_off[NTOT] = ETOT;
}

__global__ void scatter_all_kernel(const int* __restrict__ e0, const int* __restrict__ e1,
                                   const int* __restrict__ e2, const int* __restrict__ e3) {
    int e = blockIdx.x * blockDim.x + threadIdx.x;
    if (e >= ETOT) return;
    int r, off, E, dt_off, kroff;
    const int* ep;
    edge_decode(e, e0, e1, e2, e3, r, off, ep, E, dt_off, kroff);
    int pos = atomicAdd(&g_cursor[dt_off + ep[E + off]], 1);
    g_csr[pos] = (r << 20) | (kroff + ep[off]);
}

// ---------------- tensor-core GEMM core ----------------
#define LDSM4(r, addr) \
    asm volatile("ldmatrix.sync.aligned.m8n8.x4.shared.b16 {%0,%1,%2,%3}, [%4];" \
        : "=r"((r)[0]), "=r"((r)[1]), "=r"((r)[2]), "=r"((r)[3]) : "r"(addr))

#define MMA16816(c, a0, a1, a2, a3, b0, b1) \
    asm volatile("mma.sync.aligned.m16n8k16.row.col.f32.bf16.bf16.f32 " \
        "{%0,%1,%2,%3}, {%4,%5,%6,%7}, {%8,%9}, {%0,%1,%2,%3};" \
        : "+f"((c)[0]), "+f"((c)[1]), "+f"((c)[2]), "+f"((c)[3]) \
        : "r"(a0), "r"(a1), "r"(a2), "r"(a3), "r"(b0), "r"(b1))

__device__ __forceinline__ void cp16(__nv_bfloat16* dst, const __nv_bfloat16* src,
                                     int srcsize) {
    unsigned d = (unsigned)__cvta_generic_to_shared(dst);
    asm volatile("cp.async.cg.shared.global [%0], [%1], 16, %2;"
                 :: "r"(d), "l"(src), "r"(srcsize));
}
#define CP_COMMIT() asm volatile("cp.async.commit_group;")
#define CP_WAIT(n)  asm volatile("cp.async.wait_group %0;" :: "n"(n))

__device__ __forceinline__ void gemm_core(long a_row_off, long b_off,
                                          int bm, int bn, int M,
                                          __nv_bfloat16* smem,
                                          float acc[4][4][4]) {
    int t = threadIdx.x;
    int lane = t & 31, wid = t >> 5;
    int wm = (wid & 1) * 64, wn = (wid >> 1) * 32;

#pragma unroll
    for (int a = 0; a < 4; a++)
#pragma unroll
        for (int b = 0; b < 4; b++)
#pragma unroll
            for (int c = 0; c < 4; c++) acc[a][b][c] = 0.f;

    // initial load, chunk 0
#pragma unroll
    for (int i = 0; i < 4; i++) {
        int id = t + i * 256;
        int j = id & 3, m = (id >> 2) & 127, pl = id >> 9;
        const __nv_bfloat16* srcA = pl ? g_al : g_ah;
        int gr = bm + m;
        cp16(smem + pl * PLANE + m * BKPAD + j * 8,
             srcA + (a_row_off + gr) * 128 + j * 8, (gr < M) ? 16 : 0);
    }
#pragma unroll
    for (int i = 0; i < 4; i++) {
        int id = t + i * 256;
        int j = id & 3, n = (id >> 2) & 127, pl = id >> 9;
        const __nv_bfloat16* srcB = pl ? g_wl : g_wh;
        cp16(smem + (2 + pl) * PLANE + n * BKPAD + j * 8,
             srcB + b_off + (long)(bn + n) * 128 + j * 8, 16);
    }
    CP_COMMIT();

    for (int ci = 0; ci < 4; ci++) {
        if (ci < 3) {
            int kc = (ci + 1) * 32;
            __nv_bfloat16* nb = smem + ((ci + 1) & 1) * 4 * PLANE;
#pragma unroll
            for (int i = 0; i < 4; i++) {
                int id = t + i * 256;
                int j = id & 3, m = (id >> 2) & 127, pl = id >> 9;
                const __nv_bfloat16* srcA = pl ? g_al : g_ah;
                int gr = bm + m;
                cp16(nb + pl * PLANE + m * BKPAD + j * 8,
                     srcA + (a_row_off + gr) * 128 + kc + j * 8, (gr < M) ? 16 : 0);
            }
#pragma unroll
            for (int i = 0; i < 4; i++) {
                int id = t + i * 256;
                int j = id & 3, n = (id >> 2) & 127, pl = id >> 9;
                const __nv_bfloat16* srcB = pl ? g_wl : g_wh;
                cp16(nb + (2 + pl) * PLANE + n * BKPAD + j * 8,
                     srcB + b_off + (long)(bn + n) * 128 + kc + j * 8, 16);
            }
            CP_COMMIT();
            CP_WAIT(1);
        } else {
            CP_WAIT(0);
        }
        __syncthreads();

        const __nv_bfloat16* buf = smem + (ci & 1) * 4 * PLANE;
        const __nv_bfloat16* sAh = buf;
        const __nv_bfloat16* sAl = buf + PLANE;
        const __nv_bfloat16* sBh = buf + 2 * PLANE;
        const __nv_bfloat16* sBl = buf + 3 * PLANE;

#pragma unroll
        for (int k16 = 0; k16 < 32; k16 += 16) {
            unsigned af[4][2][4];
            int arow = wm + (lane & 15);
            int akoff = k16 + (lane >> 4) * 8;
#pragma unroll
            for (int mi = 0; mi < 4; mi++) {
                unsigned ah = (unsigned)__cvta_generic_to_shared(
                    sAh + (arow + mi * 16) * BKPAD + akoff);
                unsigned al = (unsigned)__cvta_generic_to_shared(
                    sAl + (arow + mi * 16) * BKPAD + akoff);
                LDSM4(af[mi][0], ah);
                LDSM4(af[mi][1], al);
            }
#pragma unroll
            for (int p = 0; p < 2; p++) {
                int nrow = wn + p * 16 + ((lane >> 4) & 1) * 8 + (lane & 7);
                int bkoff = k16 + ((lane >> 3) & 1) * 8;
                unsigned bh[4], bl[4];
                LDSM4(bh, (unsigned)__cvta_generic_to_shared(sBh + nrow * BKPAD + bkoff));
                LDSM4(bl, (unsigned)__cvta_generic_to_shared(sBl + nrow * BKPAD + bkoff));
                // sweep 1: A-hi x B-hi (8 independent accumulators)
#pragma unroll
                for (int mi = 0; mi < 4; mi++) {
                    MMA16816(acc[mi][2 * p],     af[mi][0][0], af[mi][0][1], af[mi][0][2], af[mi][0][3], bh[0], bh[1]);
                    MMA16816(acc[mi][2 * p + 1], af[mi][0][0], af[mi][0][1], af[mi][0][2], af[mi][0][3], bh[2], bh[3]);
                }
                // sweep 2: A-hi x B-lo
#pragma unroll
                for (int mi = 0; mi < 4; mi++) {
                    MMA16816(acc[mi][2 * p],     af[mi][0][0], af[mi][0][1], af[mi][0][2], af[mi][0][3], bl[0], bl[1]);
                    MMA16816(acc[mi][2 * p + 1], af[mi][0][0], af[mi][0][1], af[mi][0][2], af[mi][0][3], bl[2], bl[3]);
                }
                // sweep 3: A-lo x B-hi
#pragma unroll
                for (int mi = 0; mi < 4; mi++) {
                    MMA16816(acc[mi][2 * p],     af[mi][1][0], af[mi][1][1], af[mi][1][2], af[mi][1][3], bh[0], bh[1]);
                    MMA16816(acc[mi][2 * p + 1], af[mi][1][0], af[mi][1][1], af[mi][1][2], af[mi][1][3], bh[2], bh[3]);
                }
            }
        }
        __syncthreads();
    }
}

// combined qkv GEMM: one launch covers all 3 types
__global__ __launch_bounds__(256, 2)
void mma_qkv_kernel(int l) {
    extern __shared__ __align__(16) __nv_bfloat16 smem[];
    int bid = blockIdx.x;
    int t, nt, mt;
    if (bid < QKV_B0)                { t = 0; nt = bid % 5; mt = bid / 5; }
    else if (bid < QKV_B0 + QKV_B1)  { t = 1; nt = 0; mt = bid - QKV_B0; }
    else { int b = bid - QKV_B0 - QKV_B1; t = 2; nt = b % 5; mt = b / 5; }

    int M = (t == 0) ? 50000 : (t == 1 ? 20000 : 10000);
    long offs = (t == 0) ? 0 : (t == 1 ? 50000 : 70000);
    long kroffA = (t == 0) ? 0 : 100000;
    long kroffB = (t == 0) ? 50000 : 110000;
    int bm = mt * 128, bn = nt * 128;
    int lt = l * NTYPE + t;

    float acc[4][4][4];
    gemm_core(offs, (long)lt * W2PER, bm, bn, M, smem, acc);

    int lane = threadIdx.x & 31, wid = threadIdx.x >> 5;
    int wm = (wid & 1) * 64, wn = (wid >> 1) * 32;
    const float* bias = g_b2 + (long)lt * 5 * FF;
#pragma unroll
    for (int mi = 0; mi < 4; mi++) {
#pragma unroll
        for (int nj = 0; nj < 4; nj++) {
            int rbase = bm + wm + mi * 16 + (lane >> 2);
            int col = bn + wn + nj * 8 + (lane & 3) * 2;
            float2 b2 = *(const float2*)&bias[col];
#pragma unroll
            for (int h = 0; h < 2; h++) {
                int gr = rbase + h * 8;
                if (gr >= M) continue;
                float o0 = acc[mi][nj][h * 2 + 0] + b2.x;
                float o1 = acc[mi][nj][h * 2 + 1] + b2.y;
                int seg = col >> 7, cc = col & 127;
                if (seg == 0) {
                    *(float2*)&g_q[(offs + gr) * 128 + cc] = make_float2(o0, o1);
                } else {
                    __half2 hv = __floats2half2_rn(o0, o1);
                    long roff = ((seg == 1 || seg == 3) ? kroffA : kroffB) + gr;
                    if (seg <= 2)
                        *(__half2*)&g_krh[roff * 128 + cc] = hv;
                    else
                        *(__half2*)&g_vrh[roff * 128 + cc] = hv;
                }
            }
        }
    }
}

// combined out GEMM: one launch covers all 3 types
__global__ __launch_bounds__(256, 2)
void mma_out_kernel(int l, float* __restrict__ Cbase,
                    const float* __restrict__ Xbase,
                    const float* __restrict__ bout,
                    const float* __restrict__ skip, int xsplit) {
    extern __shared__ __align__(16) __nv_bfloat16 smem[];
    int bid = blockIdx.x;
    int t, mt;
    if (bid < MT0)            { t = 0; mt = bid; }
    else if (bid < MT0 + MT1) { t = 1; mt = bid - MT0; }
    else                      { t = 2; mt = bid - MT0 - MT1; }

    int M = (t == 0) ? 50000 : (t == 1 ? 20000 : 10000);
    long offs = (t == 0) ? 0 : (t == 1 ? 50000 : 70000);
    int bm = mt * 128;
    int lt = l * NTYPE + t;

    float acc[4][4][4];
    gemm_core(offs, (long)W2TOT + (long)lt * FF * FF, bm, 0, M, smem, acc);

    int lane = threadIdx.x & 31, wid = threadIdx.x >> 5;
    int wm = (wid & 1) * 64, wn = (wid >> 1) * 32;
    const float* bias = bout + (long)lt * FF;
    float sv = skip[lt];
    float s = 1.f / (1.f + expf(-sv));
    float oms = 1.f - s;
    float* C = Cbase + offs * FF;
    const float* X = Xbase + offs * FF;
#pragma unroll
    for (int mi = 0; mi < 4; mi++) {
#pragma unroll
        for (int nj = 0; nj < 4; nj++) {
            int rbase = bm + wm + mi * 16 + (lane >> 2);
            int col = wn + nj * 8 + (lane & 3) * 2;
            float2 b2 = *(const float2*)&bias[col];
#pragma unroll
            for (int h = 0; h < 2; h++) {
                int gr = rbase + h * 8;
                if (gr >= M) continue;
                float o0 = acc[mi][nj][h * 2 + 0] + b2.x;
                float o1 = acc[mi][nj][h * 2 + 1] + b2.y;
                float2 xv = *(const float2*)&X[(long)gr * 128 + col];
                float n0 = s * o0 + oms * xv.x;
                float n1 = s * o1 + oms * xv.y;
                float r0 = fmaxf(n0, 0.f) + xv.x;
                float r1 = fmaxf(n1, 0.f) + xv.y;
                *(float2*)&C[(long)gr * 128 + col] = make_float2(r0, r1);
                if (xsplit) {
                    long pidx = (offs + gr) * 128 + col;
                    __nv_bfloat16 h0 = __float2bfloat16_rn(r0);
                    __nv_bfloat16 h1 = __float2bfloat16_rn(r1);
                    __nv_bfloat16 l0 = __float2bfloat16_rn(r0 - __bfloat162float(h0));
                    __nv_bfloat16 l1 = __float2bfloat16_rn(r1 - __bfloat162float(h1));
                    __nv_bfloat162 hv; hv.x = h0; hv.y = h1;
                    __nv_bfloat162 lv; lv.x = l0; lv.y = l1;
                    *(__nv_bfloat162*)&g_ah[pidx] = hv;
                    *(__nv_bfloat162*)&g_al[pidx] = lv;
                }
            }
        }
    }
}

// ---------------- fused edge phase (head-per-lane) ----------------
__device__ __forceinline__ void unpack8(uint4 u, float* f) {
    float2 a = __half22float2(*(__half2*)&u.x);
    float2 b = __half22float2(*(__half2*)&u.y);
    float2 c = __half22float2(*(__half2*)&u.z);
    float2 d = __half22float2(*(__half2*)&u.w);
    f[0] = a.x; f[1] = a.y; f[2] = b.x; f[3] = b.y;
    f[4] = c.x; f[5] = c.y; f[6] = d.x; f[7] = d.y;
}

__global__ __launch_bounds__(256)
void edge_fused_kernel(const float* __restrict__ prel, int l) {
    int warp = (blockIdx.x * blockDim.x + threadIdx.x) >> 5;
    int lane = threadIdx.x & 31;
    if (warp >= NTOT) return;
    int g = lane >> 3;      // edge slot 0..3
    int h = lane & 7;       // head
    int o0 = g_off[warp], o1 = g_off[warp + 1];

    float q[16];
    const float4* qp = (const float4*)(g_q + (long)warp * FF + h * 16);
#pragma unroll
    for (int i = 0; i < 4; i++) *(float4*)&q[i * 4] = qp[i];

    float prh[NREL];
#pragma unroll
    for (int r = 0; r < NREL; r++)
        prh[r] = prel[(l * NREL + r) * HH + h] * 0.25f;

    float acc[16];
#pragma unroll
    for (int i = 0; i < 16; i++) acc[i] = 0.f;
    float denom = 0.f;

    for (int base = o0; base < o1; base += 4) {
        int j = base + g;
        bool act = (j < o1);
        int cv = act ? g_csr[j] : g_csr[base];
        long row = (long)(cv & 0xFFFFF) * FF + h * 16;
        int rel = cv >> 20;
        uint4 k0 = *(const uint4*)(g_krh + row);
        uint4 k1 = *(const uint4*)(g_krh + row + 8);
        uint4 v0 = *(const uint4*)(g_vrh + row);
        uint4 v1 = *(const uint4*)(g_vrh + row + 8);
        float kf[16];
        unpack8(k0, kf);
        unpack8(k1, kf + 8);
        float p = 0.f;
#pragma unroll
        for (int i = 0; i < 16; i++) p += q[i] * kf[i];
        float ex = act ? __expf(p * prh[rel]) : 0.f;
        float vf[16];
        unpack8(v0, vf);
        unpack8(v1, vf + 8);
#pragma unroll
        for (int i = 0; i < 16; i++) acc[i] += ex * vf[i];
        denom += ex;
    }

#pragma unroll
    for (int i = 0; i < 16; i++) {
        acc[i] += __shfl_xor_sync(0xFFFFFFFFu, acc[i], 8);
        acc[i] += __shfl_xor_sync(0xFFFFFFFFu, acc[i], 16);
    }
    denom += __shfl_xor_sync(0xFFFFFFFFu, denom, 8);
    denom += __shfl_xor_sync(0xFFFFFFFFu, denom, 16);

    if (g == 0) {
        float inv = (o1 > o0) ? 1.f / denom : 0.f;
        __nv_bfloat16 hb[16], lb[16];
#pragma unroll
        for (int i = 0; i < 16; i++) {
            float o = gelu_f(acc[i] * inv);
            hb[i] = __float2bfloat16_rn(o);
            lb[i] = __float2bfloat16_rn(o - __bfloat162float(hb[i]));
        }
        long idx = (long)warp * FF + h * 16;
        *(uint4*)&g_ah[idx]     = *(const uint4*)&hb[0];
        *(uint4*)&g_ah[idx + 8] = *(const uint4*)&hb[8];
        *(uint4*)&g_al[idx]     = *(const uint4*)&lb[0];
        *(uint4*)&g_al[idx + 8] = *(const uint4*)&lb[8];
    }
}

// ---------------- launch ----------------
extern "C" void kernel_launch(void* const* d_in, const int* in_sizes, int n_in,
                              void* d_out, int out_size) {
    const float* xg   = (const float*)d_in[0];
    const float* xd   = (const float*)d_in[1];
    const float* xr   = (const float*)d_in[2];
    const float* Wkqv = (const float*)d_in[3];
    const float* bkqv = (const float*)d_in[4];
    const float* Ak   = (const float*)d_in[5];
    const float* Av   = (const float*)d_in[6];
    const float* prel = (const float*)d_in[7];
    const float* Wout = (const float*)d_in[8];
    const float* bout = (const float*)d_in[9];
    const float* skip = (const float*)d_in[10];
    const int* e0 = (const int*)d_in[11];
    const int* e1 = (const int*)d_in[12];
    const int* e2 = (const int*)d_in[13];
    const int* e3 = (const int*)d_in[14];
    float* outp = (float*)d_out;

    const int SPLIT_BLOCKS = (NTOT * FF / 8 + 255) / 256;

    float* d_x0; cudaGetSymbolAddress((void**)&d_x0, g_x0);
    float* d_x1; cudaGetSymbolAddress((void**)&d_x1, g_x1);

    // one-time side stream + events for CSR-build overlap (created outside
    // graph capture, on the correctness run). Fallback: everything on stream 0.
    static cudaStream_t sB = 0;
    static cudaEvent_t evF = 0, evJ = 0;
    static int init_done = 0;
    if (!init_done) {
        init_done = 1;
        if (cudaStreamCreateWithFlags(&sB, cudaStreamNonBlocking) != cudaSuccess) sB = 0;
        if (sB) {
            if (cudaEventCreateWithFlags(&evF, cudaEventDisableTiming) != cudaSuccess ||
                cudaEventCreateWithFlags(&evJ, cudaEventDisableTiming) != cudaSuccess) {
                sB = 0;
            }
        }
        cudaFuncSetAttribute(mma_qkv_kernel, cudaFuncAttributeMaxDynamicSharedMemorySize, GEMM_SMEM);
        cudaFuncSetAttribute(mma_out_kernel, cudaFuncAttributeMaxDynamicSharedMemorySize, GEMM_SMEM);
    }

    cudaStream_t sCSR = sB ? sB : (cudaStream_t)0;
    if (sB) {
        cudaEventRecord(evF, 0);
        cudaStreamWaitEvent(sB, evF, 0);
    }

    // stream B (or inline): CSR build — independent of all setup on stream 0
    zero_deg_kernel<<<(NTOT + 255) / 256, 256, 0, sCSR>>>();
    hist_all_kernel<<<(ETOT + 255) / 256, 256, 0, sCSR>>>(e0, e1, e2, e3);
    scan_kernel<<<1, 1024, 0, sCSR>>>();
    scatter_all_kernel<<<(ETOT + 255) / 256, 256, 0, sCSR>>>(e0, e1, e2, e3);
    if (sB) cudaEventRecord(evJ, sB);

    // stream 0: activation/weight prep + layer pipeline
    copyin_split_kernel<<<SPLIT_BLOCKS, 256>>>(xg, xd, xr);
    fold_kernel<<<(W2TOT + 255) / 256, 256>>>(Wkqv, Ak, Av);
    foldb_kernel<<<(NLAYER * NTYPE * 5 * FF + 255) / 256, 256>>>(bkqv, Ak, Av);
    splitw_kernel<<<(OUTW_ELEMS + 255) / 256, 256>>>(Wout);

    for (int l = 0; l < NLAYER; l++) {
        mma_qkv_kernel<<<QKV_BLOCKS, 256, GEMM_SMEM>>>(l);
        if (l == 0 && sB) cudaStreamWaitEvent(0, evJ, 0);   // CSR ready before first edge pass
        edge_fused_kernel<<<NTOT / 8, 256>>>(prel, l);
        float* cdst = (l == 0) ? d_x1 : outp;
        const float* xcur = (l == 0) ? d_x0 : d_x1;
        mma_out_kernel<<<OUT_BLOCKS, 256, GEMM_SMEM>>>(
            l, cdst, xcur, bout, skip, (l == 0) ? 1 : 0);
    }
    (void)in_sizes; (void)n_in; (void)out_size;
}

// round 15
// speedup vs baseline: 2.2102x; 1.1595x over previous
#include <cuda_runtime.h>
#include <cuda_bf16.h>
#include <cuda_fp16.h>
#include <math.h>

// ---------------- problem constants ----------------
#define HH 8
#define DD 16
#define FF 128
#define F3 384
#define NLAYER 2
#define NTYPE 3
#define NREL 4
#define NTOT 80000
#define KRTOT 120000
#define ETOT 600000
#define BKPAD 40           // smem k-stride in halves (80 bytes): conflict-free ldmatrix
#define PLANE (128 * BKPAD)            // 5120 halves = 10KB
#define GEMM_SMEM (2 * 2 * PLANE * 2)  // 40KB: 2 buffers x (A,B) x fp16

// folded qkv weights: [L][T][5 segs][128 n][128 k]
#define W2SEG 16384
#define W2PER (5 * W2SEG)
#define W2TOT (NLAYER * NTYPE * W2PER)          // 491520
#define OUTW_ELEMS (NLAYER * NTYPE * FF * FF)   //  98304
#define WALL (W2TOT + OUTW_ELEMS)

// block-mapping constants
#define MT0 391
#define MT1 157
#define MT2 79
#define QKV_B0 (5 * MT0)
#define QKV_B1 MT1
#define QKV_BLOCKS (QKV_B0 + QKV_B1 + 5 * MT2)   // 2507
#define OUT_BLOCKS (MT0 + MT1 + MT2)             // 627

// ---------------- device scratch ----------------
__device__ __align__(16) float g_x0[NTOT * FF];
__device__ __align__(16) float g_x1[NTOT * FF];
__device__ __align__(16) float g_q[NTOT * FF];
__device__ __align__(16) __half g_krh[KRTOT * FF];
__device__ __align__(16) __half g_vrh[KRTOT * FF];
__device__ __align__(16) __half g_af[NTOT * FF];   // fp16 activation plane (GEMM A)
__device__ __align__(16) __half g_wf[WALL];        // fp16 weights, k-major
__device__ float g_b2[NLAYER * NTYPE * 5 * FF];
__device__ int g_deg[NTOT];
__device__ int g_off[NTOT + 1];
__device__ int g_cursor[NTOT];
__device__ int g_csr[ETOT];      // (r << 20) | (kroff + src)

__device__ __forceinline__ float gelu_f(float x) {
    return 0.5f * x * (1.f + erff(x * 0.70710678118654752440f));
}

// ---------------- setup kernels ----------------

__global__ void copyin_split_kernel(const float* __restrict__ xg,
                                    const float* __restrict__ xd,
                                    const float* __restrict__ xr) {
    int tid = blockIdx.x * blockDim.x + threadIdx.x;
    long i8 = (long)tid * 8;
    if (i8 >= (long)NTOT * FF) return;
    const long n1 = 50000L * FF, n2 = 70000L * FF;
    const float* src;
    long off;
    if (i8 < n1)      { src = xg; off = i8; }
    else if (i8 < n2) { src = xd; off = i8 - n1; }
    else              { src = xr; off = i8 - n2; }
    float v[8];
    *(float4*)&v[0] = *(const float4*)&src[off];
    *(float4*)&v[4] = *(const float4*)&src[off + 4];
    *(float4*)&g_x0[i8]     = *(const float4*)&v[0];
    *(float4*)&g_x0[i8 + 4] = *(const float4*)&v[4];
    __half h[8];
#pragma unroll
    for (int j = 0; j < 8; j++) h[j] = __float2half_rn(v[j]);
    *(uint4*)&g_af[i8] = *(const uint4*)&h[0];
}

__global__ void fold_kernel(const float* __restrict__ Wkqv,
                            const float* __restrict__ Ak,
                            const float* __restrict__ Av) {
    int idx = blockIdx.x * blockDim.x + threadIdx.x;
    if (idx >= W2TOT) return;
    int k = idx & 127;
    int n = (idx >> 7) & 127;
    int sl = idx >> 14;
    int seg = sl % 5, lt = sl / 5;
    int l = lt / NTYPE, t = lt % NTYPE;
    const float* W = Wkqv + (long)lt * FF * F3;
    float val = 0.f;
    if (seg == 0) {
        val = W[(long)k * F3 + FF + n];
    } else if (t != 1) {
        int r = (t == 0 ? 0 : 2) + ((seg == 2 || seg == 4) ? 1 : 0);
        int h = n >> 4, e = n & 15;
        const float* A = ((seg <= 2) ? Ak : Av) +
                         ((long)(l * NREL + r) * HH + h) * DD * DD;
        int colbase = (seg <= 2 ? 0 : 2 * FF) + h * DD;
#pragma unroll
        for (int d = 0; d < DD; d++)
            val += W[(long)k * F3 + colbase + d] * A[d * DD + e];
    }
    g_wf[idx] = __float2half_rn(val);
}

__global__ void foldb_kernel(const float* __restrict__ bkqv,
                             const float* __restrict__ Ak,
                             const float* __restrict__ Av) {
    int idx = blockIdx.x * blockDim.x + threadIdx.x;
    if (idx >= NLAYER * NTYPE * 5 * FF) return;
    int n = idx & 127;
    int sl = idx >> 7;
    int seg = sl % 5, lt = sl / 5;
    int l = lt / NTYPE, t = lt % NTYPE;
    const float* b = bkqv + (long)lt * F3;
    float val = 0.f;
    if (seg == 0) {
        val = b[FF + n];
    } else if (t != 1) {
        int r = (t == 0 ? 0 : 2) + ((seg == 2 || seg == 4) ? 1 : 0);
        int h = n >> 4, e = n & 15;
        const float* A = ((seg <= 2) ? Ak : Av) +
                         ((long)(l * NREL + r) * HH + h) * DD * DD;
        int colbase = (seg <= 2 ? 0 : 2 * FF) + h * DD;
#pragma unroll
        for (int d = 0; d < DD; d++)
            val += b[colbase + d] * A[d * DD + e];
    }
    g_b2[idx] = val;
}

__global__ void splitw_kernel(const float* __restrict__ Wout) {
    int idx = blockIdx.x * blockDim.x + threadIdx.x;
    if (idx >= OUTW_ELEMS) return;
    int lt = idx / (FF * FF);
    int rem = idx - lt * (FF * FF);
    int n = rem / FF, k = rem % FF;
    float val = Wout[(long)lt * FF * FF + (long)k * FF + n];
    g_wf[W2TOT + idx] = __float2half_rn(val);
}

// ---------------- CSR build ----------------

__global__ void zero_deg_kernel() {
    int i = blockIdx.x * blockDim.x + threadIdx.x;
    if (i < NTOT) g_deg[i] = 0;
}

__device__ __forceinline__ void edge_decode(int e, const int* e0, const int* e1,
                                            const int* e2, const int* e3,
                                            int& r, int& off, const int*& ep,
                                            int& E, int& dt_off, int& kroff) {
    if (e < 300000)      { r = 0; off = e;          ep = e0; E = 300000; dt_off = 0;     kroff = 0; }
    else if (e < 450000) { r = 1; off = e - 300000; ep = e1; E = 150000; dt_off = 50000; kroff = 50000; }
    else if (e < 550000) { r = 2; off = e - 450000; ep = e2; E = 100000; dt_off = 0;     kroff = 100000; }
    else                 { r = 3; off = e - 550000; ep = e3; E = 50000;  dt_off = 50000; kroff = 110000; }
}

__global__ void hist_all_kernel(const int* __restrict__ e0, const int* __restrict__ e1,
                                const int* __restrict__ e2, const int* __restrict__ e3) {
    int e = blockIdx.x * blockDim.x + threadIdx.x;
    if (e >= ETOT) return;
    int r, off, E, dt_off, kroff;
    const int* ep;
    edge_decode(e, e0, e1, e2, e3, r, off, ep, E, dt_off, kroff);
    atomicAdd(&g_deg[dt_off + ep[E + off]], 1);
}

__global__ void scan_kernel() {
    __shared__ int s[1024];
    int t = threadIdx.x;
    const int CHUNK = 79;
    int base = t * CHUNK;
    int sum = 0;
    for (int i = 0; i < CHUNK; i++) {
        int idx = base + i;
        if (idx < NTOT) sum += g_deg[idx];
    }
    s[t] = sum;
    __syncthreads();
    for (int d = 1; d < 1024; d <<= 1) {
        int v = (t >= d) ? s[t - d] : 0;
        __syncthreads();
        s[t] += v;
        __syncthreads();
    }
    int run = (t == 0) ? 0 : s[t - 1];
    for (int i = 0; i < CHUNK; i++) {
        int idx = base + i;
        if (idx < NTOT) {
            g_off[idx] = run;
            g_cursor[idx] = run;
            run += g_deg[idx];
        }
    }
    if (t == 0) g_off[NTOT] = ETOT;
}

__global__ void scatter_all_kernel(const int* __restrict__ e0, const int* __restrict__ e1,
                                   const int* __restrict__ e2, const int* __restrict__ e3) {
    int e = blockIdx.x * blockDim.x + threadIdx.x;
    if (e >= ETOT) return;
    int r, off, E, dt_off, kroff;
    const int* ep;
    edge_decode(e, e0, e1, e2, e3, r, off, ep, E, dt_off, kroff);
    int pos = atomicAdd(&g_cursor[dt_off + ep[E + off]], 1);
    g_csr[pos] = (r << 20) | (kroff + ep[off]);
}

// ---------------- tensor-core GEMM core (fp16 single-plane) ----------------
#define LDSM4(r, addr) \
    asm volatile("ldmatrix.sync.aligned.m8n8.x4.shared.b16 {%0,%1,%2,%3}, [%4];" \
        : "=r"((r)[0]), "=r"((r)[1]), "=r"((r)[2]), "=r"((r)[3]) : "r"(addr))

#define MMAF16(c, a0, a1, a2, a3, b0, b1) \
    asm volatile("mma.sync.aligned.m16n8k16.row.col.f32.f16.f16.f32 " \
        "{%0,%1,%2,%3}, {%4,%5,%6,%7}, {%8,%9}, {%0,%1,%2,%3};" \
        : "+f"((c)[0]), "+f"((c)[1]), "+f"((c)[2]), "+f"((c)[3]) \
        : "r"(a0), "r"(a1), "r"(a2), "r"(a3), "r"(b0), "r"(b1))

__device__ __forceinline__ void cp16(__half* dst, const __half* src, int srcsize) {
    unsigned d = (unsigned)__cvta_generic_to_shared(dst);
    asm volatile("cp.async.cg.shared.global [%0], [%1], 16, %2;"
                 :: "r"(d), "l"(src), "r"(srcsize));
}
#define CP_COMMIT() asm volatile("cp.async.commit_group;")
#define CP_WAIT(n)  asm volatile("cp.async.wait_group %0;" :: "n"(n))

__device__ __forceinline__ void gemm_load(long a_row_off, long b_off,
                                          int bm, int bn, int M, int kc,
                                          __half* buf) {
    int t = threadIdx.x;
#pragma unroll
    for (int i = 0; i < 2; i++) {
        int id = t + i * 256;
        int j = id & 3, m = id >> 2;
        int gr = bm + m;
        cp16(buf + m * BKPAD + j * 8,
             g_af + (a_row_off + gr) * 128 + kc + j * 8, (gr < M) ? 16 : 0);
    }
#pragma unroll
    for (int i = 0; i < 2; i++) {
        int id = t + i * 256;
        int j = id & 3, n = id >> 2;
        cp16(buf + PLANE + n * BKPAD + j * 8,
             g_wf + b_off + (long)(bn + n) * 128 + kc + j * 8, 16);
    }
}

__device__ __forceinline__ void gemm_core(long a_row_off, long b_off,
                                          int bm, int bn, int M,
                                          __half* smem,
                                          float acc[4][4][4]) {
    int lane = threadIdx.x & 31, wid = threadIdx.x >> 5;
    int wm = (wid & 1) * 64, wn = (wid >> 1) * 32;

#pragma unroll
    for (int a = 0; a < 4; a++)
#pragma unroll
        for (int b = 0; b < 4; b++)
#pragma unroll
            for (int c = 0; c < 4; c++) acc[a][b][c] = 0.f;

    gemm_load(a_row_off, b_off, bm, bn, M, 0, smem);
    CP_COMMIT();

    for (int ci = 0; ci < 4; ci++) {
        if (ci < 3) {
            gemm_load(a_row_off, b_off, bm, bn, M, (ci + 1) * 32,
                      smem + ((ci + 1) & 1) * 2 * PLANE);
            CP_COMMIT();
            CP_WAIT(1);
        } else {
            CP_WAIT(0);
        }
        __syncthreads();

        const __half* buf = smem + (ci & 1) * 2 * PLANE;
        const __half* sA = buf;
        const __half* sB = buf + PLANE;

#pragma unroll
        for (int k16 = 0; k16 < 32; k16 += 16) {
            unsigned af[4][4];
            int arow = wm + (lane & 15);
            int akoff = k16 + (lane >> 4) * 8;
#pragma unroll
            for (int mi = 0; mi < 4; mi++) {
                LDSM4(af[mi], (unsigned)__cvta_generic_to_shared(
                    sA + (arow + mi * 16) * BKPAD + akoff));
            }
#pragma unroll
            for (int p = 0; p < 2; p++) {
                int nrow = wn + p * 16 + ((lane >> 4) & 1) * 8 + (lane & 7);
                int bkoff = k16 + ((lane >> 3) & 1) * 8;
                unsigned bf[4];
                LDSM4(bf, (unsigned)__cvta_generic_to_shared(sB + nrow * BKPAD + bkoff));
                // 8 independent accumulators per sweep
#pragma unroll
                for (int mi = 0; mi < 4; mi++) {
                    MMAF16(acc[mi][2 * p],     af[mi][0], af[mi][1], af[mi][2], af[mi][3], bf[0], bf[1]);
                    MMAF16(acc[mi][2 * p + 1], af[mi][0], af[mi][1], af[mi][2], af[mi][3], bf[2], bf[3]);
                }
            }
        }
        __syncthreads();
    }
}

// combined qkv GEMM: one launch covers all 3 types
__global__ __launch_bounds__(256, 2)
void mma_qkv_kernel(int l) {
    extern __shared__ __align__(16) __half smem[];
    int bid = blockIdx.x;
    int t, nt, mt;
    if (bid < QKV_B0)                { t = 0; nt = bid % 5; mt = bid / 5; }
    else if (bid < QKV_B0 + QKV_B1)  { t = 1; nt = 0; mt = bid - QKV_B0; }
    else { int b = bid - QKV_B0 - QKV_B1; t = 2; nt = b % 5; mt = b / 5; }

    int M = (t == 0) ? 50000 : (t == 1 ? 20000 : 10000);
    long offs = (t == 0) ? 0 : (t == 1 ? 50000 : 70000);
    long kroffA = (t == 0) ? 0 : 100000;
    long kroffB = (t == 0) ? 50000 : 110000;
    int bm = mt * 128, bn = nt * 128;
    int lt = l * NTYPE + t;

    float acc[4][4][4];
    gemm_core(offs, (long)lt * W2PER, bm, bn, M, smem, acc);

    int lane = threadIdx.x & 31, wid = threadIdx.x >> 5;
    int wm = (wid & 1) * 64, wn = (wid >> 1) * 32;
    const float* bias = g_b2 + (long)lt * 5 * FF;
#pragma unroll
    for (int mi = 0; mi < 4; mi++) {
#pragma unroll
        for (int nj = 0; nj < 4; nj++) {
            int rbase = bm + wm + mi * 16 + (lane >> 2);
            int col = bn + wn + nj * 8 + (lane & 3) * 2;
            float2 b2 = *(const float2*)&bias[col];
#pragma unroll
            for (int h = 0; h < 2; h++) {
                int gr = rbase + h * 8;
                if (gr >= M) continue;
                float o0 = acc[mi][nj][h * 2 + 0] + b2.x;
                float o1 = acc[mi][nj][h * 2 + 1] + b2.y;
                int seg = col >> 7, cc = col & 127;
                if (seg == 0) {
                    *(float2*)&g_q[(offs + gr) * 128 + cc] = make_float2(o0, o1);
                } else {
                    __half2 hv = __floats2half2_rn(o0, o1);
                    long roff = ((seg == 1 || seg == 3) ? kroffA : kroffB) + gr;
                    if (seg <= 2)
                        *(__half2*)&g_krh[roff * 128 + cc] = hv;
                    else
                        *(__half2*)&g_vrh[roff * 128 + cc] = hv;
                }
            }
        }
    }
}

// combined out GEMM: one launch covers all 3 types
__global__ __launch_bounds__(256, 2)
void mma_out_kernel(int l, float* __restrict__ Cbase,
                    const float* __restrict__ Xbase,
                    const float* __restrict__ bout,
                    const float* __restrict__ skip, int xsplit) {
    extern __shared__ __align__(16) __half smem[];
    int bid = blockIdx.x;
    int t, mt;
    if (bid < MT0)            { t = 0; mt = bid; }
    else if (bid < MT0 + MT1) { t = 1; mt = bid - MT0; }
    else                      { t = 2; mt = bid - MT0 - MT1; }

    int M = (t == 0) ? 50000 : (t == 1 ? 20000 : 10000);
    long offs = (t == 0) ? 0 : (t == 1 ? 50000 : 70000);
    int bm = mt * 128;
    int lt = l * NTYPE + t;

    float acc[4][4][4];
    gemm_core(offs, (long)W2TOT + (long)lt * FF * FF, bm, 0, M, smem, acc);

    int lane = threadIdx.x & 31, wid = threadIdx.x >> 5;
    int wm = (wid & 1) * 64, wn = (wid >> 1) * 32;
    const float* bias = bout + (long)lt * FF;
    float sv = skip[lt];
    float s = 1.f / (1.f + expf(-sv));
    float oms = 1.f - s;
    float* C = Cbase + offs * FF;
    const float* X = Xbase + offs * FF;
#pragma unroll
    for (int mi = 0; mi < 4; mi++) {
#pragma unroll
        for (int nj = 0; nj < 4; nj++) {
            int rbase = bm + wm + mi * 16 + (lane >> 2);
            int col = wn + nj * 8 + (lane & 3) * 2;
            float2 b2 = *(const float2*)&bias[col];
#pragma unroll
            for (int h = 0; h < 2; h++) {
                int gr = rbase + h * 8;
                if (gr >= M) continue;
                float o0 = acc[mi][nj][h * 2 + 0] + b2.x;
                float o1 = acc[mi][nj][h * 2 + 1] + b2.y;
                float2 xv = *(const float2*)&X[(long)gr * 128 + col];
                float n0 = s * o0 + oms * xv.x;
                float n1 = s * o1 + oms * xv.y;
                float r0 = fmaxf(n0, 0.f) + xv.x;
                float r1 = fmaxf(n1, 0.f) + xv.y;
                *(float2*)&C[(long)gr * 128 + col] = make_float2(r0, r1);
                if (xsplit) {
                    *(__half2*)&g_af[(offs + gr) * 128 + col] =
                        __floats2half2_rn(r0, r1);
                }
            }
        }
    }
}

// ---------------- fused edge phase (head-per-lane) ----------------
__device__ __forceinline__ void unpack8(uint4 u, float* f) {
    float2 a = __half22float2(*(__half2*)&u.x);
    float2 b = __half22float2(*(__half2*)&u.y);
    float2 c = __half22float2(*(__half2*)&u.z);
    float2 d = __half22float2(*(__half2*)&u.w);
    f[0] = a.x; f[1] = a.y; f[2] = b.x; f[3] = b.y;
    f[4] = c.x; f[5] = c.y; f[6] = d.x; f[7] = d.y;
}

__global__ __launch_bounds__(256)
void edge_fused_kernel(const float* __restrict__ prel, int l) {
    int warp = (blockIdx.x * blockDim.x + threadIdx.x) >> 5;
    int lane = threadIdx.x & 31;
    if (warp >= NTOT) return;
    int g = lane >> 3;      // edge slot 0..3
    int h = lane & 7;       // head
    int o0 = g_off[warp], o1 = g_off[warp + 1];

    float q[16];
    const float4* qp = (const float4*)(g_q + (long)warp * FF + h * 16);
#pragma unroll
    for (int i = 0; i < 4; i++) *(float4*)&q[i * 4] = qp[i];

    float prh[NREL];
#pragma unroll
    for (int r = 0; r < NREL; r++)
        prh[r] = prel[(l * NREL + r) * HH + h] * 0.25f;

    float acc[16];
#pragma unroll
    for (int i = 0; i < 16; i++) acc[i] = 0.f;
    float denom = 0.f;

    for (int base = o0; base < o1; base += 4) {
        int j = base + g;
        bool act = (j < o1);
        int cv = act ? g_csr[j] : g_csr[base];
        long row = (long)(cv & 0xFFFFF) * FF + h * 16;
        int rel = cv >> 20;
        uint4 k0 = *(const uint4*)(g_krh + row);
        uint4 k1 = *(const uint4*)(g_krh + row + 8);
        uint4 v0 = *(const uint4*)(g_vrh + row);
        uint4 v1 = *(const uint4*)(g_vrh + row + 8);
        float kf[16];
        unpack8(k0, kf);
        unpack8(k1, kf + 8);
        float p = 0.f;
#pragma unroll
        for (int i = 0; i < 16; i++) p += q[i] * kf[i];
        float ex = act ? __expf(p * prh[rel]) : 0.f;
        float vf[16];
        unpack8(v0, vf);
        unpack8(v1, vf + 8);
#pragma unroll
        for (int i = 0; i < 16; i++) acc[i] += ex * vf[i];
        denom += ex;
    }

#pragma unroll
    for (int i = 0; i < 16; i++) {
        acc[i] += __shfl_xor_sync(0xFFFFFFFFu, acc[i], 8);
        acc[i] += __shfl_xor_sync(0xFFFFFFFFu, acc[i], 16);
    }
    denom += __shfl_xor_sync(0xFFFFFFFFu, denom, 8);
    denom += __shfl_xor_sync(0xFFFFFFFFu, denom, 16);

    if (g == 0) {
        float inv = (o1 > o0) ? 1.f / denom : 0.f;
        __half hb[16];
#pragma unroll
        for (int i = 0; i < 16; i++)
            hb[i] = __float2half_rn(gelu_f(acc[i] * inv));
        long idx = (long)warp * FF + h * 16;
        *(uint4*)&g_af[idx]     = *(const uint4*)&hb[0];
        *(uint4*)&g_af[idx + 8] = *(const uint4*)&hb[8];
    }
}

// ---------------- launch ----------------
extern "C" void kernel_launch(void* const* d_in, const int* in_sizes, int n_in,
                              void* d_out, int out_size) {
    const float* xg   = (const float*)d_in[0];
    const float* xd   = (const float*)d_in[1];
    const float* xr   = (const float*)d_in[2];
    const float* Wkqv = (const float*)d_in[3];
    const float* bkqv = (const float*)d_in[4];
    const float* Ak   = (const float*)d_in[5];
    const float* Av   = (const float*)d_in[6];
    const float* prel = (const float*)d_in[7];
    const float* Wout = (const float*)d_in[8];
    const float* bout = (const float*)d_in[9];
    const float* skip = (const float*)d_in[10];
    const int* e0 = (const int*)d_in[11];
    const int* e1 = (const int*)d_in[12];
    const int* e2 = (const int*)d_in[13];
    const int* e3 = (const int*)d_in[14];
    float* outp = (float*)d_out;

    const int SPLIT_BLOCKS = (NTOT * FF / 8 + 255) / 256;

    float* d_x0; cudaGetSymbolAddress((void**)&d_x0, g_x0);
    float* d_x1; cudaGetSymbolAddress((void**)&d_x1, g_x1);

    // one-time side stream + events for CSR-build overlap
    static cudaStream_t sB = 0;
    static cudaEvent_t evF = 0, evJ = 0;
    static int init_done = 0;
    if (!init_done) {
        init_done = 1;
        if (cudaStreamCreateWithFlags(&sB, cudaStreamNonBlocking) != cudaSuccess) sB = 0;
        if (sB) {
            if (cudaEventCreateWithFlags(&evF, cudaEventDisableTiming) != cudaSuccess ||
                cudaEventCreateWithFlags(&evJ, cudaEventDisableTiming) != cudaSuccess) {
                sB = 0;
            }
        }
        cudaFuncSetAttribute(mma_qkv_kernel, cudaFuncAttributeMaxDynamicSharedMemorySize, GEMM_SMEM);
        cudaFuncSetAttribute(mma_out_kernel, cudaFuncAttributeMaxDynamicSharedMemorySize, GEMM_SMEM);
    }

    cudaStream_t sCSR = sB ? sB : (cudaStream_t)0;
    if (sB) {
        cudaEventRecord(evF, 0);
        cudaStreamWaitEvent(sB, evF, 0);
    }

    // stream B (or inline): CSR build
    zero_deg_kernel<<<(NTOT + 255) / 256, 256, 0, sCSR>>>();
    hist_all_kernel<<<(ETOT + 255) / 256, 256, 0, sCSR>>>(e0, e1, e2, e3);
    scan_kernel<<<1, 1024, 0, sCSR>>>();
    scatter_all_kernel<<<(ETOT + 255) / 256, 256, 0, sCSR>>>(e0, e1, e2, e3);
    if (sB) cudaEventRecord(evJ, sB);

    // stream 0: activation/weight prep + layer pipeline
    copyin_split_kernel<<<SPLIT_BLOCKS, 256>>>(xg, xd, xr);
    fold_kernel<<<(W2TOT + 255) / 256, 256>>>(Wkqv, Ak, Av);
    foldb_kernel<<<(NLAYER * NTYPE * 5 * FF + 255) / 256, 256>>>(bkqv, Ak, Av);
    splitw_kernel<<<(OUTW_ELEMS + 255) / 256, 256>>>(Wout);

    for (int l = 0; l < NLAYER; l++) {
        mma_qkv_kernel<<<QKV_BLOCKS, 256, GEMM_SMEM>>>(l);
        if (l == 0 && sB) cudaStreamWaitEvent(0, evJ, 0);
        edge_fused_kernel<<<NTOT / 8, 256>>>(prel, l);
        float* cdst = (l == 0) ? d_x1 : outp;
        const float* xcur = (l == 0) ? d_x0 : d_x1;
        mma_out_kernel<<<OUT_BLOCKS, 256, GEMM_SMEM>>>(
            l, cdst, xcur, bout, skip, (l == 0) ? 1 : 0);
    }
    (void)in_sizes; (void)n_in; (void)out_size;
}

// round 16
// speedup vs baseline: 2.3236x; 1.0513x over previous
#include <cuda_runtime.h>
#include <cuda_bf16.h>
#include <cuda_fp16.h>
#include <math.h>

// ---------------- problem constants ----------------
#define HH 8
#define DD 16
#define FF 128
#define F3 384
#define NLAYER 2
#define NTYPE 3
#define NREL 4
#define NTOT 80000
#define KRTOT 120000
#define ETOT 600000
#define BKPAD 40           // smem k-stride in halves (80 bytes): conflict-free ldmatrix
#define PLANE (128 * BKPAD)            // 5120 halves = 10KB
#define NSTAGE 3
#define GEMM_SMEM (NSTAGE * 2 * PLANE * 2)  // 60KB: 3 stages x (A,B) x fp16

// folded qkv weights: [L][T][5 segs][128 n][128 k]
#define W2SEG 16384
#define W2PER (5 * W2SEG)
#define W2TOT (NLAYER * NTYPE * W2PER)          // 491520
#define OUTW_ELEMS (NLAYER * NTYPE * FF * FF)   //  98304
#define WALL (W2TOT + OUTW_ELEMS)

// block-mapping constants
#define MT0 391
#define MT1 157
#define MT2 79
#define QKV_B0 (5 * MT0)
#define QKV_B1 MT1
#define QKV_BLOCKS (QKV_B0 + QKV_B1 + 5 * MT2)   // 2507
#define OUT_BLOCKS (MT0 + MT1 + MT2)             // 627

// ---------------- device scratch ----------------
__device__ __align__(16) float g_x0[NTOT * FF];
__device__ __align__(16) float g_x1[NTOT * FF];
__device__ __align__(16) __half g_qh[NTOT * FF];   // fp16 q
__device__ __align__(16) __half g_krh[KRTOT * FF];
__device__ __align__(16) __half g_vrh[KRTOT * FF];
__device__ __align__(16) __half g_af[NTOT * FF];   // fp16 activation plane (GEMM A)
__device__ __align__(16) __half g_wf[WALL];        // fp16 weights, k-major
__device__ float g_b2[NLAYER * NTYPE * 5 * FF];
__device__ int g_deg[NTOT];
__device__ int g_off[NTOT + 1];
__device__ int g_cursor[NTOT];
__device__ int g_csr[ETOT];      // (r << 20) | (kroff + src)

__device__ __forceinline__ float gelu_f(float x) {
    return 0.5f * x * (1.f + erff(x * 0.70710678118654752440f));
}

// ---------------- setup kernels ----------------

__global__ void copyin_split_kernel(const float* __restrict__ xg,
                                    const float* __restrict__ xd,
                                    const float* __restrict__ xr) {
    int tid = blockIdx.x * blockDim.x + threadIdx.x;
    long i8 = (long)tid * 8;
    if (i8 >= (long)NTOT * FF) return;
    const long n1 = 50000L * FF, n2 = 70000L * FF;
    const float* src;
    long off;
    if (i8 < n1)      { src = xg; off = i8; }
    else if (i8 < n2) { src = xd; off = i8 - n1; }
    else              { src = xr; off = i8 - n2; }
    float v[8];
    *(float4*)&v[0] = *(const float4*)&src[off];
    *(float4*)&v[4] = *(const float4*)&src[off + 4];
    *(float4*)&g_x0[i8]     = *(const float4*)&v[0];
    *(float4*)&g_x0[i8 + 4] = *(const float4*)&v[4];
    __half h[8];
#pragma unroll
    for (int j = 0; j < 8; j++) h[j] = __float2half_rn(v[j]);
    *(uint4*)&g_af[i8] = *(const uint4*)&h[0];
}

__global__ void fold_kernel(const float* __restrict__ Wkqv,
                            const float* __restrict__ Ak,
                            const float* __restrict__ Av) {
    int idx = blockIdx.x * blockDim.x + threadIdx.x;
    if (idx >= W2TOT) return;
    int k = idx & 127;
    int n = (idx >> 7) & 127;
    int sl = idx >> 14;
    int seg = sl % 5, lt = sl / 5;
    int l = lt / NTYPE, t = lt % NTYPE;
    const float* W = Wkqv + (long)lt * FF * F3;
    float val = 0.f;
    if (seg == 0) {
        val = W[(long)k * F3 + FF + n];
    } else if (t != 1) {
        int r = (t == 0 ? 0 : 2) + ((seg == 2 || seg == 4) ? 1 : 0);
        int h = n >> 4, e = n & 15;
        const float* A = ((seg <= 2) ? Ak : Av) +
                         ((long)(l * NREL + r) * HH + h) * DD * DD;
        int colbase = (seg <= 2 ? 0 : 2 * FF) + h * DD;
#pragma unroll
        for (int d = 0; d < DD; d++)
            val += W[(long)k * F3 + colbase + d] * A[d * DD + e];
    }
    g_wf[idx] = __float2half_rn(val);
}

__global__ void foldb_kernel(const float* __restrict__ bkqv,
                             const float* __restrict__ Ak,
                             const float* __restrict__ Av) {
    int idx = blockIdx.x * blockDim.x + threadIdx.x;
    if (idx >= NLAYER * NTYPE * 5 * FF) return;
    int n = idx & 127;
    int sl = idx >> 7;
    int seg = sl % 5, lt = sl / 5;
    int l = lt / NTYPE, t = lt % NTYPE;
    const float* b = bkqv + (long)lt * F3;
    float val = 0.f;
    if (seg == 0) {
        val = b[FF + n];
    } else if (t != 1) {
        int r = (t == 0 ? 0 : 2) + ((seg == 2 || seg == 4) ? 1 : 0);
        int h = n >> 4, e = n & 15;
        const float* A = ((seg <= 2) ? Ak : Av) +
                         ((long)(l * NREL + r) * HH + h) * DD * DD;
        int colbase = (seg <= 2 ? 0 : 2 * FF) + h * DD;
#pragma unroll
        for (int d = 0; d < DD; d++)
            val += b[colbase + d] * A[d * DD + e];
    }
    g_b2[idx] = val;
}

__global__ void splitw_kernel(const float* __restrict__ Wout) {
    int idx = blockIdx.x * blockDim.x + threadIdx.x;
    if (idx >= OUTW_ELEMS) return;
    int lt = idx / (FF * FF);
    int rem = idx - lt * (FF * FF);
    int n = rem / FF, k = rem % FF;
    float val = Wout[(long)lt * FF * FF + (long)k * FF + n];
    g_wf[W2TOT + idx] = __float2half_rn(val);
}

// ---------------- CSR build ----------------

__global__ void zero_deg_kernel() {
    int i = blockIdx.x * blockDim.x + threadIdx.x;
    if (i < NTOT) g_deg[i] = 0;
}

__device__ __forceinline__ void edge_decode(int e, const int* e0, const int* e1,
                                            const int* e2, const int* e3,
                                            int& r, int& off, const int*& ep,
                                            int& E, int& dt_off, int& kroff) {
    if (e < 300000)      { r = 0; off = e;          ep = e0; E = 300000; dt_off = 0;     kroff = 0; }
    else if (e < 450000) { r = 1; off = e - 300000; ep = e1; E = 150000; dt_off = 50000; kroff = 50000; }
    else if (e < 550000) { r = 2; off = e - 450000; ep = e2; E = 100000; dt_off = 0;     kroff = 100000; }
    else                 { r = 3; off = e - 550000; ep = e3; E = 50000;  dt_off = 50000; kroff = 110000; }
}

__global__ void hist_all_kernel(const int* __restrict__ e0, const int* __restrict__ e1,
                                const int* __restrict__ e2, const int* __restrict__ e3) {
    int e = blockIdx.x * blockDim.x + threadIdx.x;
    if (e >= ETOT) return;
    int r, off, E, dt_off, kroff;
    const int* ep;
    edge_decode(e, e0, e1, e2, e3, r, off, ep, E, dt_off, kroff);
    atomicAdd(&g_deg[dt_off + ep[E + off]], 1);
}

__global__ void scan_kernel() {
    __shared__ int s[1024];
    int t = threadIdx.x;
    const int CHUNK = 79;
    int base = t * CHUNK;
    int sum = 0;
    for (int i = 0; i < CHUNK; i++) {
        int idx = base + i;
        if (idx < NTOT) sum += g_deg[idx];
    }
    s[t] = sum;
    __syncthreads();
    for (int d = 1; d < 1024; d <<= 1) {
        int v = (t >= d) ? s[t - d] : 0;
        __syncthreads();
        s[t] += v;
        __syncthreads();
    }
    int run = (t == 0) ? 0 : s[t - 1];
    for (int i = 0; i < CHUNK; i++) {
        int idx = base + i;
        if (idx < NTOT) {
            g_off[idx] = run;
            g_cursor[idx] = run;
            run += g_deg[idx];
        }
    }
    if (t == 0) g_off[NTOT] = ETOT;
}

__global__ void scatter_all_kernel(const int* __restrict__ e0, const int* __restrict__ e1,
                                   const int* __restrict__ e2, const int* __restrict__ e3) {
    int e = blockIdx.x * blockDim.x + threadIdx.x;
    if (e >= ETOT) return;
    int r, off, E, dt_off, kroff;
    const int* ep;
    edge_decode(e, e0, e1, e2, e3, r, off, ep, E, dt_off, kroff);
    int pos = atomicAdd(&g_cursor[dt_off + ep[E + off]], 1);
    g_csr[pos] = (r << 20) | (kroff + ep[off]);
}

// ---------------- tensor-core GEMM core (fp16, 3-stage cp.async) ----------
#define LDSM4(r, addr) \
    asm volatile("ldmatrix.sync.aligned.m8n8.x4.shared.b16 {%0,%1,%2,%3}, [%4];" \
        : "=r"((r)[0]), "=r"((r)[1]), "=r"((r)[2]), "=r"((r)[3]) : "r"(addr))

#define MMAF16(c, a0, a1, a2, a3, b0, b1) \
    asm volatile("mma.sync.aligned.m16n8k16.row.col.f32.f16.f16.f32 " \
        "{%0,%1,%2,%3}, {%4,%5,%6,%7}, {%8,%9}, {%0,%1,%2,%3};" \
        : "+f"((c)[0]), "+f"((c)[1]), "+f"((c)[2]), "+f"((c)[3]) \
        : "r"(a0), "r"(a1), "r"(a2), "r"(a3), "r"(b0), "r"(b1))

__device__ __forceinline__ void cp16(__half* dst, const __half* src, int srcsize) {
    unsigned d = (unsigned)__cvta_generic_to_shared(dst);
    asm volatile("cp.async.cg.shared.global [%0], [%1], 16, %2;"
                 :: "r"(d), "l"(src), "r"(srcsize));
}
#define CP_COMMIT() asm volatile("cp.async.commit_group;")
#define CP_WAIT(n)  asm volatile("cp.async.wait_group %0;" :: "n"(n))

__device__ __forceinline__ void gemm_load(long a_row_off, long b_off,
                                          int bm, int bn, int M, int kc,
                                          __half* buf) {
    int t = threadIdx.x;
#pragma unroll
    for (int i = 0; i < 2; i++) {
        int id = t + i * 256;
        int j = id & 3, m = id >> 2;
        int gr = bm + m;
        cp16(buf + m * BKPAD + j * 8,
             g_af + (a_row_off + gr) * 128 + kc + j * 8, (gr < M) ? 16 : 0);
    }
#pragma unroll
    for (int i = 0; i < 2; i++) {
        int id = t + i * 256;
        int j = id & 3, n = id >> 2;
        cp16(buf + PLANE + n * BKPAD + j * 8,
             g_wf + b_off + (long)(bn + n) * 128 + kc + j * 8, 16);
    }
}

__device__ __forceinline__ void gemm_core(long a_row_off, long b_off,
                                          int bm, int bn, int M,
                                          __half* smem,
                                          float acc[4][4][4]) {
    int lane = threadIdx.x & 31, wid = threadIdx.x >> 5;
    int wm = (wid & 1) * 64, wn = (wid >> 1) * 32;

#pragma unroll
    for (int a = 0; a < 4; a++)
#pragma unroll
        for (int b = 0; b < 4; b++)
#pragma unroll
            for (int c = 0; c < 4; c++) acc[a][b][c] = 0.f;

    gemm_load(a_row_off, b_off, bm, bn, M, 0, smem);
    CP_COMMIT();
    gemm_load(a_row_off, b_off, bm, bn, M, 32, smem + 2 * PLANE);
    CP_COMMIT();

    for (int ci = 0; ci < 4; ci++) {
        if (ci < 2) {
            gemm_load(a_row_off, b_off, bm, bn, M, (ci + 2) * 32,
                      smem + ((ci + 2) % NSTAGE) * 2 * PLANE);
            CP_COMMIT();
            CP_WAIT(2);
        } else if (ci == 2) {
            CP_WAIT(1);
        } else {
            CP_WAIT(0);
        }
        __syncthreads();

        const __half* buf = smem + (ci % NSTAGE) * 2 * PLANE;
        const __half* sA = buf;
        const __half* sB = buf + PLANE;

#pragma unroll
        for (int k16 = 0; k16 < 32; k16 += 16) {
            unsigned af[4][4];
            int arow = wm + (lane & 15);
            int akoff = k16 + (lane >> 4) * 8;
#pragma unroll
            for (int mi = 0; mi < 4; mi++) {
                LDSM4(af[mi], (unsigned)__cvta_generic_to_shared(
                    sA + (arow + mi * 16) * BKPAD + akoff));
            }
#pragma unroll
            for (int p = 0; p < 2; p++) {
                int nrow = wn + p * 16 + ((lane >> 4) & 1) * 8 + (lane & 7);
                int bkoff = k16 + ((lane >> 3) & 1) * 8;
                unsigned bf[4];
                LDSM4(bf, (unsigned)__cvta_generic_to_shared(sB + nrow * BKPAD + bkoff));
#pragma unroll
                for (int mi = 0; mi < 4; mi++) {
                    MMAF16(acc[mi][2 * p],     af[mi][0], af[mi][1], af[mi][2], af[mi][3], bf[0], bf[1]);
                    MMAF16(acc[mi][2 * p + 1], af[mi][0], af[mi][1], af[mi][2], af[mi][3], bf[2], bf[3]);
                }
            }
        }
        __syncthreads();
    }
}

// combined qkv GEMM: one launch covers all 3 types
__global__ __launch_bounds__(256, 2)
void mma_qkv_kernel(int l) {
    extern __shared__ __align__(16) __half smem[];
    int bid = blockIdx.x;
    int t, nt, mt;
    if (bid < QKV_B0)                { t = 0; nt = bid % 5; mt = bid / 5; }
    else if (bid < QKV_B0 + QKV_B1)  { t = 1; nt = 0; mt = bid - QKV_B0; }
    else { int b = bid - QKV_B0 - QKV_B1; t = 2; nt = b % 5; mt = b / 5; }

    int M = (t == 0) ? 50000 : (t == 1 ? 20000 : 10000);
    long offs = (t == 0) ? 0 : (t == 1 ? 50000 : 70000);
    long kroffA = (t == 0) ? 0 : 100000;
    long kroffB = (t == 0) ? 50000 : 110000;
    int bm = mt * 128, bn = nt * 128;
    int lt = l * NTYPE + t;

    float acc[4][4][4];
    gemm_core(offs, (long)lt * W2PER, bm, bn, M, smem, acc);

    int lane = threadIdx.x & 31, wid = threadIdx.x >> 5;
    int wm = (wid & 1) * 64, wn = (wid >> 1) * 32;
    const float* bias = g_b2 + (long)lt * 5 * FF;
#pragma unroll
    for (int mi = 0; mi < 4; mi++) {
#pragma unroll
        for (int nj = 0; nj < 4; nj++) {
            int rbase = bm + wm + mi * 16 + (lane >> 2);
            int col = bn + wn + nj * 8 + (lane & 3) * 2;
            float2 b2 = *(const float2*)&bias[col];
#pragma unroll
            for (int h = 0; h < 2; h++) {
                int gr = rbase + h * 8;
                if (gr >= M) continue;
                float o0 = acc[mi][nj][h * 2 + 0] + b2.x;
                float o1 = acc[mi][nj][h * 2 + 1] + b2.y;
                int seg = col >> 7, cc = col & 127;
                __half2 hv = __floats2half2_rn(o0, o1);
                if (seg == 0) {
                    *(__half2*)&g_qh[(offs + gr) * 128 + cc] = hv;
                } else {
                    long roff = ((seg == 1 || seg == 3) ? kroffA : kroffB) + gr;
                    if (seg <= 2)
                        *(__half2*)&g_krh[roff * 128 + cc] = hv;
                    else
                        *(__half2*)&g_vrh[roff * 128 + cc] = hv;
                }
            }
        }
    }
}

// combined out GEMM: one launch covers all 3 types
__global__ __launch_bounds__(256, 2)
void mma_out_kernel(int l, float* __restrict__ Cbase,
                    const float* __restrict__ Xbase,
                    const float* __restrict__ bout,
                    const float* __restrict__ skip, int xsplit) {
    extern __shared__ __align__(16) __half smem[];
    int bid = blockIdx.x;
    int t, mt;
    if (bid < MT0)            { t = 0; mt = bid; }
    else if (bid < MT0 + MT1) { t = 1; mt = bid - MT0; }
    else                      { t = 2; mt = bid - MT0 - MT1; }

    int M = (t == 0) ? 50000 : (t == 1 ? 20000 : 10000);
    long offs = (t == 0) ? 0 : (t == 1 ? 50000 : 70000);
    int bm = mt * 128;
    int lt = l * NTYPE + t;

    float acc[4][4][4];
    gemm_core(offs, (long)W2TOT + (long)lt * FF * FF, bm, 0, M, smem, acc);

    int lane = threadIdx.x & 31, wid = threadIdx.x >> 5;
    int wm = (wid & 1) * 64, wn = (wid >> 1) * 32;
    const float* bias = bout + (long)lt * FF;
    float sv = skip[lt];
    float s = 1.f / (1.f + expf(-sv));
    float oms = 1.f - s;
    float* C = Cbase + offs * FF;
    const float* X = Xbase + offs * FF;
#pragma unroll
    for (int mi = 0; mi < 4; mi++) {
#pragma unroll
        for (int nj = 0; nj < 4; nj++) {
            int rbase = bm + wm + mi * 16 + (lane >> 2);
            int col = wn + nj * 8 + (lane & 3) * 2;
            float2 b2 = *(const float2*)&bias[col];
#pragma unroll
            for (int h = 0; h < 2; h++) {
                int gr = rbase + h * 8;
                if (gr >= M) continue;
                float o0 = acc[mi][nj][h * 2 + 0] + b2.x;
                float o1 = acc[mi][nj][h * 2 + 1] + b2.y;
                float2 xv = *(const float2*)&X[(long)gr * 128 + col];
                float n0 = s * o0 + oms * xv.x;
                float n1 = s * o1 + oms * xv.y;
                float r0 = fmaxf(n0, 0.f) + xv.x;
                float r1 = fmaxf(n1, 0.f) + xv.y;
                *(float2*)&C[(long)gr * 128 + col] = make_float2(r0, r1);
                if (xsplit) {
                    *(__half2*)&g_af[(offs + gr) * 128 + col] =
                        __floats2half2_rn(r0, r1);
                }
            }
        }
    }
}

// ---------------- fused edge phase (head-per-lane, CSR pipelined) --------
__device__ __forceinline__ void unpack8(uint4 u, float* f) {
    float2 a = __half22float2(*(__half2*)&u.x);
    float2 b = __half22float2(*(__half2*)&u.y);
    float2 c = __half22float2(*(__half2*)&u.z);
    float2 d = __half22float2(*(__half2*)&u.w);
    f[0] = a.x; f[1] = a.y; f[2] = b.x; f[3] = b.y;
    f[4] = c.x; f[5] = c.y; f[6] = d.x; f[7] = d.y;
}

__global__ __launch_bounds__(256)
void edge_fused_kernel(const float* __restrict__ prel, int l) {
    int warp = (blockIdx.x * blockDim.x + threadIdx.x) >> 5;
    int lane = threadIdx.x & 31;
    if (warp >= NTOT) return;
    int g = lane >> 3;      // edge slot 0..3
    int h = lane & 7;       // head
    int o0 = g_off[warp], o1 = g_off[warp + 1];

    float q[16];
    {
        uint4 q0 = *(const uint4*)(g_qh + (long)warp * FF + h * 16);
        uint4 q1 = *(const uint4*)(g_qh + (long)warp * FF + h * 16 + 8);
        unpack8(q0, q);
        unpack8(q1, q + 8);
    }

    float prh[NREL];
#pragma unroll
    for (int r = 0; r < NREL; r++)
        prh[r] = prel[(l * NREL + r) * HH + h] * 0.25f;

    float acc[16];
#pragma unroll
    for (int i = 0; i < 16; i++) acc[i] = 0.f;
    float denom = 0.f;

    // software-pipelined CSR index: prefetch next iteration's entry
    int cvn = (o0 + g < o1) ? g_csr[o0 + g] : 0;
    for (int base = o0; base < o1; base += 4) {
        int cv = cvn;
        bool act = (base + g < o1);
        int nj = base + 4 + g;
        if (nj < o1) cvn = g_csr[nj];
        long row = (long)(cv & 0xFFFFF) * FF + h * 16;
        int rel = cv >> 20;
        uint4 k0 = *(const uint4*)(g_krh + row);
        uint4 k1 = *(const uint4*)(g_krh + row + 8);
        uint4 v0 = *(const uint4*)(g_vrh + row);
        uint4 v1 = *(const uint4*)(g_vrh + row + 8);
        float kf[16];
        unpack8(k0, kf);
        unpack8(k1, kf + 8);
        float p = 0.f;
#pragma unroll
        for (int i = 0; i < 16; i++) p += q[i] * kf[i];
        float ex = act ? __expf(p * prh[rel]) : 0.f;
        float vf[16];
        unpack8(v0, vf);
        unpack8(v1, vf + 8);
#pragma unroll
        for (int i = 0; i < 16; i++) acc[i] += ex * vf[i];
        denom += ex;
    }

#pragma unroll
    for (int i = 0; i < 16; i++) {
        acc[i] += __shfl_xor_sync(0xFFFFFFFFu, acc[i], 8);
        acc[i] += __shfl_xor_sync(0xFFFFFFFFu, acc[i], 16);
    }
    denom += __shfl_xor_sync(0xFFFFFFFFu, denom, 8);
    denom += __shfl_xor_sync(0xFFFFFFFFu, denom, 16);

    if (g == 0) {
        float inv = (o1 > o0) ? 1.f / denom : 0.f;
        __half hb[16];
#pragma unroll
        for (int i = 0; i < 16; i++)
            hb[i] = __float2half_rn(gelu_f(acc[i] * inv));
        long idx = (long)warp * FF + h * 16;
        *(uint4*)&g_af[idx]     = *(const uint4*)&hb[0];
        *(uint4*)&g_af[idx + 8] = *(const uint4*)&hb[8];
    }
}

// ---------------- launch ----------------
extern "C" void kernel_launch(void* const* d_in, const int* in_sizes, int n_in,
                              void* d_out, int out_size) {
    const float* xg   = (const float*)d_in[0];
    const float* xd   = (const float*)d_in[1];
    const float* xr   = (const float*)d_in[2];
    const float* Wkqv = (const float*)d_in[3];
    const float* bkqv = (const float*)d_in[4];
    const float* Ak   = (const float*)d_in[5];
    const float* Av   = (const float*)d_in[6];
    const float* prel = (const float*)d_in[7];
    const float* Wout = (const float*)d_in[8];
    const float* bout = (const float*)d_in[9];
    const float* skip = (const float*)d_in[10];
    const int* e0 = (const int*)d_in[11];
    const int* e1 = (const int*)d_in[12];
    const int* e2 = (const int*)d_in[13];
    const int* e3 = (const int*)d_in[14];
    float* outp = (float*)d_out;

    const int SPLIT_BLOCKS = (NTOT * FF / 8 + 255) / 256;

    float* d_x0; cudaGetSymbolAddress((void**)&d_x0, g_x0);
    float* d_x1; cudaGetSymbolAddress((void**)&d_x1, g_x1);

    // one-time side stream + events for CSR-build overlap
    static cudaStream_t sB = 0;
    static cudaEvent_t evF = 0, evJ = 0;
    static int init_done = 0;
    if (!init_done) {
        init_done = 1;
        if (cudaStreamCreateWithFlags(&sB, cudaStreamNonBlocking) != cudaSuccess) sB = 0;
        if (sB) {
            if (cudaEventCreateWithFlags(&evF, cudaEventDisableTiming) != cudaSuccess ||
                cudaEventCreateWithFlags(&evJ, cudaEventDisableTiming) != cudaSuccess) {
                sB = 0;
            }
        }
        cudaFuncSetAttribute(mma_qkv_kernel, cudaFuncAttributeMaxDynamicSharedMemorySize, GEMM_SMEM);
        cudaFuncSetAttribute(mma_out_kernel, cudaFuncAttributeMaxDynamicSharedMemorySize, GEMM_SMEM);
    }

    cudaStream_t sCSR = sB ? sB : (cudaStream_t)0;
    if (sB) {
        cudaEventRecord(evF, 0);
        cudaStreamWaitEvent(sB, evF, 0);
    }

    // stream B (or inline): CSR build
    zero_deg_kernel<<<(NTOT + 255) / 256, 256, 0, sCSR>>>();
    hist_all_kernel<<<(ETOT + 255) / 256, 256, 0, sCSR>>>(e0, e1, e2, e3);
    scan_kernel<<<1, 1024, 0, sCSR>>>();
    scatter_all_kernel<<<(ETOT + 255) / 256, 256, 0, sCSR>>>(e0, e1, e2, e3);
    if (sB) cudaEventRecord(evJ, sB);

    // stream 0: activation/weight prep + layer pipeline
    copyin_split_kernel<<<SPLIT_BLOCKS, 256>>>(xg, xd, xr);
    fold_kernel<<<(W2TOT + 255) / 256, 256>>>(Wkqv, Ak, Av);
    foldb_kernel<<<(NLAYER * NTYPE * 5 * FF + 255) / 256, 256>>>(bkqv, Ak, Av);
    splitw_kernel<<<(OUTW_ELEMS + 255) / 256, 256>>>(Wout);

    for (int l = 0; l < NLAYER; l++) {
        mma_qkv_kernel<<<QKV_BLOCKS, 256, GEMM_SMEM>>>(l);
        if (l == 0 && sB) cudaStreamWaitEvent(0, evJ, 0);
        edge_fused_kernel<<<NTOT / 8, 256>>>(prel, l);
        float* cdst = (l == 0) ? d_x1 : outp;
        const float* xcur = (l == 0) ? d_x0 : d_x1;
        mma_out_kernel<<<OUT_BLOCKS, 256, GEMM_SMEM>>>(
            l, cdst, xcur, bout, skip, (l == 0) ? 1 : 0);
    }
    (void)in_sizes; (void)n_in; (void)out_size;
}